// round 1
// baseline (speedup 1.0000x reference)
#include <cuda_runtime.h>
#include <math.h>

#define T  4096
#define CH 512
#define M3 1536

// Scratch (statically allocated device globals; no runtime allocation)
__device__ float g_qkv[(size_t)2 * M3 * T];   // 48 MB
__device__ float g_a[(size_t)2 * CH * T];     // 16 MB
__device__ float g_ir[(size_t)2 * T];         // inv-rms * sqrt(C)

// ---------------------------------------------------------------------------
// Kernel 1: per-(b,t) RMS statistics. invrms includes the sqrt(C) factor.
// ---------------------------------------------------------------------------
__global__ void rms_kernel(const float* __restrict__ x) {
    int i = blockIdx.x * blockDim.x + threadIdx.x;   // 0..8191
    int b = i >> 12;
    int t = i & (T - 1);
    const float* xp = x + (size_t)b * CH * T + t;
    float s = 0.f;
#pragma unroll 8
    for (int c = 0; c < CH; c++) {
        float v = xp[(size_t)c * T];
        s = fmaf(v, v, s);
    }
    // sqrt(512) = 22.627416997969522
    g_ir[i] = 22.62741699796952f * rsqrtf(s * (1.0f / CH) + 1e-8f);
}

// ---------------------------------------------------------------------------
// Kernel 2: QKV GEMM. out[b,o,t] = sum_c W[o,c] * (x[b,c,t]*nw[c]*ir[b,t]) + bias[o]
// 64x64 tile, K-tile 16, 256 threads, 4x4 per thread.
// ---------------------------------------------------------------------------
__global__ void qkv_gemm(const float* __restrict__ W, const float* __restrict__ x,
                         const float* __restrict__ nw, const float* __restrict__ bias) {
    __shared__ float As[16][65];
    __shared__ float Bs[16][65];
    int b  = blockIdx.z;
    int m0 = blockIdx.y << 6;
    int t0 = blockIdx.x << 6;
    int tid = threadIdx.x;
    int ar = tid >> 2,  ac = (tid & 3)  << 2;
    int br = tid >> 4,  bc = (tid & 15) << 2;
    int tm = tid >> 4,  tn = tid & 15;
    const float* xb = x + (size_t)b * CH * T;
    float4 ir4 = *(const float4*)&g_ir[b * T + t0 + bc];
    float acc[4][4] = {};

    for (int k0 = 0; k0 < CH; k0 += 16) {
        float4 a4 = *(const float4*)&W[(size_t)(m0 + ar) * CH + k0 + ac];
        As[ac + 0][ar] = a4.x; As[ac + 1][ar] = a4.y;
        As[ac + 2][ar] = a4.z; As[ac + 3][ar] = a4.w;
        float nv = nw[k0 + br];
        float4 b4 = *(const float4*)&xb[(size_t)(k0 + br) * T + t0 + bc];
        Bs[br][bc + 0] = b4.x * nv * ir4.x;
        Bs[br][bc + 1] = b4.y * nv * ir4.y;
        Bs[br][bc + 2] = b4.z * nv * ir4.z;
        Bs[br][bc + 3] = b4.w * nv * ir4.w;
        __syncthreads();
#pragma unroll
        for (int k = 0; k < 16; k++) {
            float av[4], bv[4];
#pragma unroll
            for (int i = 0; i < 4; i++) av[i] = As[k][(tm << 2) + i];
#pragma unroll
            for (int j = 0; j < 4; j++) bv[j] = Bs[k][(tn << 2) + j];
#pragma unroll
            for (int i = 0; i < 4; i++)
#pragma unroll
                for (int j = 0; j < 4; j++)
                    acc[i][j] = fmaf(av[i], bv[j], acc[i][j]);
        }
        __syncthreads();
    }
#pragma unroll
    for (int i = 0; i < 4; i++) {
        int row = m0 + (tm << 2) + i;
        float bi = bias[row];
        float* op = &g_qkv[((size_t)b * M3 + row) * T + t0 + (tn << 2)];
#pragma unroll
        for (int j = 0; j < 4; j++) op[j] = acc[i][j] + bi;
    }
}

// ---------------------------------------------------------------------------
// Kernel 3: flash attention. One block = (head, 64-query tile).
// ch = 64. Q preloaded & pre-scaled by ch^-0.5. P overlays K's smem tile.
// ---------------------------------------------------------------------------
__global__ void attn_kernel() {
    extern __shared__ float sm[];
    float* Qs  = sm;                 // [64][65]  (c, t)
    float* KPs = sm + 64 * 65;       // [64][65]  K:(c,s) then P:(t,s)
    float* Vs  = sm + 2 * 64 * 65;   // [64][65]  (c, s)
    __shared__ float m_run[64], l_run[64], corr_s[64];

    int t0   = blockIdx.x << 6;
    int head = blockIdx.y;           // 0..15
    int b  = head >> 3;
    int hh = head & 7;
    const float* qb = g_qkv + ((size_t)b * M3 + hh * 192) * T;
    const float* kb = qb + (size_t)64 * T;
    const float* vb = qb + (size_t)128 * T;

    int tid = threadIdx.x;
    int tm = tid >> 4, tn = tid & 15;

    // load Q tile, pre-multiplied by scale^2 = ch^-0.5 = 0.125
#pragma unroll
    for (int i = 0; i < 16; i++) {
        int idx = tid + (i << 8);
        int c = idx >> 6, tt = idx & 63;
        Qs[c * 65 + tt] = qb[(size_t)c * T + t0 + tt] * 0.125f;
    }
    if (tid < 64) { m_run[tid] = -1e30f; l_run[tid] = 0.f; }

    float o[4][4] = {};

    for (int s0 = 0; s0 < T; s0 += 64) {
        __syncthreads();   // previous iteration's PV done before overwriting K/V
#pragma unroll
        for (int i = 0; i < 16; i++) {
            int idx = tid + (i << 8);
            int c = idx >> 6, ss = idx & 63;
            KPs[c * 65 + ss] = kb[(size_t)c * T + s0 + ss];
            Vs [c * 65 + ss] = vb[(size_t)c * T + s0 + ss];
        }
        __syncthreads();

        // S = (Q^T K) tile; thread owns rows t=4tm.., cols s=4tn..
        float acc[4][4] = {};
#pragma unroll 8
        for (int c = 0; c < 64; c++) {
            float av[4], bv[4];
#pragma unroll
            for (int i = 0; i < 4; i++) av[i] = Qs[c * 65 + (tm << 2) + i];
#pragma unroll
            for (int j = 0; j < 4; j++) bv[j] = KPs[c * 65 + (tn << 2) + j];
#pragma unroll
            for (int i = 0; i < 4; i++)
#pragma unroll
                for (int j = 0; j < 4; j++)
                    acc[i][j] = fmaf(av[i], bv[j], acc[i][j]);
        }
        __syncthreads();   // everyone done reading K before P overlays it

        // online softmax per row; rows of one tm-group live in one 16-lane group
#pragma unroll
        for (int i = 0; i < 4; i++) {
            int row = (tm << 2) + i;
            float mx = fmaxf(fmaxf(acc[i][0], acc[i][1]), fmaxf(acc[i][2], acc[i][3]));
#pragma unroll
            for (int off = 8; off; off >>= 1)
                mx = fmaxf(mx, __shfl_xor_sync(0xffffffffu, mx, off));
            float m_old = m_run[row];
            float m_new = fmaxf(m_old, mx);
            float p[4], rs = 0.f;
#pragma unroll
            for (int j = 0; j < 4; j++) { p[j] = __expf(acc[i][j] - m_new); rs += p[j]; }
#pragma unroll
            for (int off = 8; off; off >>= 1)
                rs += __shfl_xor_sync(0xffffffffu, rs, off);
            if (tn == 0) {
                float cr = __expf(m_old - m_new);
                corr_s[row] = cr;
                l_run[row] = l_run[row] * cr + rs;
                m_run[row] = m_new;
            }
#pragma unroll
            for (int j = 0; j < 4; j++)
                KPs[row * 65 + (tn << 2) + j] = p[j];   // P[t][s]
        }
        __syncthreads();

        // rescale O and accumulate O[c,t] += sum_s P[t,s] V[c,s]
        // thread owns c=4tm.., t=4tn..
        float cj[4];
#pragma unroll
        for (int j = 0; j < 4; j++) cj[j] = corr_s[(tn << 2) + j];
#pragma unroll
        for (int i = 0; i < 4; i++)
#pragma unroll
            for (int j = 0; j < 4; j++) o[i][j] *= cj[j];

#pragma unroll 8
        for (int s = 0; s < 64; s++) {
            float vv[4], pp[4];
#pragma unroll
            for (int i = 0; i < 4; i++) vv[i] = Vs[((tm << 2) + i) * 65 + s];
#pragma unroll
            for (int j = 0; j < 4; j++) pp[j] = KPs[((tn << 2) + j) * 65 + s];
#pragma unroll
            for (int i = 0; i < 4; i++)
#pragma unroll
                for (int j = 0; j < 4; j++)
                    o[i][j] = fmaf(vv[i], pp[j], o[i][j]);
        }
    }
    __syncthreads();

    float linv[4];
#pragma unroll
    for (int j = 0; j < 4; j++) linv[j] = 1.f / l_run[(tn << 2) + j];

    float* ab = g_a + ((size_t)b * CH + hh * 64) * T;
#pragma unroll
    for (int i = 0; i < 4; i++)
#pragma unroll
        for (int j = 0; j < 4; j++)
            ab[(size_t)((tm << 2) + i) * T + t0 + (tn << 2) + j] = o[i][j] * linv[j];
}

// ---------------------------------------------------------------------------
// Kernel 4: proj GEMM + bias + residual
// ---------------------------------------------------------------------------
__global__ void proj_gemm(const float* __restrict__ W, const float* __restrict__ bias,
                          const float* __restrict__ xres, float* __restrict__ out) {
    __shared__ float As[16][65];
    __shared__ float Bs[16][65];
    int b  = blockIdx.z;
    int m0 = blockIdx.y << 6;
    int t0 = blockIdx.x << 6;
    int tid = threadIdx.x;
    int ar = tid >> 2,  ac = (tid & 3)  << 2;
    int br = tid >> 4,  bc = (tid & 15) << 2;
    int tm = tid >> 4,  tn = tid & 15;
    const float* Ab = g_a + (size_t)b * CH * T;
    float acc[4][4] = {};

    for (int k0 = 0; k0 < CH; k0 += 16) {
        float4 a4 = *(const float4*)&W[(size_t)(m0 + ar) * CH + k0 + ac];
        As[ac + 0][ar] = a4.x; As[ac + 1][ar] = a4.y;
        As[ac + 2][ar] = a4.z; As[ac + 3][ar] = a4.w;
        float4 b4 = *(const float4*)&Ab[(size_t)(k0 + br) * T + t0 + bc];
        Bs[br][bc + 0] = b4.x; Bs[br][bc + 1] = b4.y;
        Bs[br][bc + 2] = b4.z; Bs[br][bc + 3] = b4.w;
        __syncthreads();
#pragma unroll
        for (int k = 0; k < 16; k++) {
            float av[4], bv[4];
#pragma unroll
            for (int i = 0; i < 4; i++) av[i] = As[k][(tm << 2) + i];
#pragma unroll
            for (int j = 0; j < 4; j++) bv[j] = Bs[k][(tn << 2) + j];
#pragma unroll
            for (int i = 0; i < 4; i++)
#pragma unroll
                for (int j = 0; j < 4; j++)
                    acc[i][j] = fmaf(av[i], bv[j], acc[i][j]);
        }
        __syncthreads();
    }
#pragma unroll
    for (int i = 0; i < 4; i++) {
        int row = m0 + (tm << 2) + i;
        float bi = bias[row];
        size_t base = ((size_t)b * CH + row) * T + t0 + (tn << 2);
#pragma unroll
        for (int j = 0; j < 4; j++)
            out[base + j] = acc[i][j] + bi + xres[base + j];
    }
}

// ---------------------------------------------------------------------------
extern "C" void kernel_launch(void* const* d_in, const int* in_sizes, int n_in,
                              void* d_out, int out_size) {
    const float* x      = (const float*)d_in[0];
    const float* nw     = (const float*)d_in[1];
    const float* qkv_w  = (const float*)d_in[2];
    const float* qkv_b  = (const float*)d_in[3];
    const float* proj_w = (const float*)d_in[4];
    const float* proj_b = (const float*)d_in[5];
    float* out = (float*)d_out;

    rms_kernel<<<32, 256>>>(x);
    qkv_gemm<<<dim3(64, 24, 2), 256>>>(qkv_w, x, nw, qkv_b);

    const int ATT_SMEM = 3 * 64 * 65 * (int)sizeof(float);   // 49920 B
    cudaFuncSetAttribute(attn_kernel, cudaFuncAttributeMaxDynamicSharedMemorySize, ATT_SMEM);
    attn_kernel<<<dim3(64, 16), 256, ATT_SMEM>>>();

    proj_gemm<<<dim3(64, 8, 2), 256>>>(proj_w, proj_b, x, out);
}

// round 2
// speedup vs baseline: 1.0554x; 1.0554x over previous
#include <cuda_runtime.h>
#include <math.h>

#define T  4096
#define CH 512
#define M3 1536

// Scratch (statically allocated device globals; no runtime allocation)
__device__ float g_qkv[(size_t)2 * M3 * T];   // 48 MB
__device__ float g_a[(size_t)2 * CH * T];     // 16 MB
__device__ float g_ir[(size_t)2 * T];         // inv-rms * sqrt(C)

// ---------------------------------------------------------------------------
// Kernel 1: per-(b,t) RMS statistics. invrms includes the sqrt(C) factor.
// ---------------------------------------------------------------------------
__global__ void rms_kernel(const float* __restrict__ x) {
    int i = blockIdx.x * blockDim.x + threadIdx.x;   // 0..8191
    int b = i >> 12;
    int t = i & (T - 1);
    const float* xp = x + (size_t)b * CH * T + t;
    float s = 0.f;
#pragma unroll 8
    for (int c = 0; c < CH; c++) {
        float v = xp[(size_t)c * T];
        s = fmaf(v, v, s);
    }
    // sqrt(512) = 22.627416997969522
    g_ir[i] = 22.62741699796952f * rsqrtf(s * (1.0f / CH) + 1e-8f);
}

// ---------------------------------------------------------------------------
// Kernel 2: QKV GEMM. out[b,o,t] = sum_c W[o,c] * (x[b,c,t]*nw[c]*ir[b,t]) + bias[o]
// 64x64 tile, K-tile 16, 256 threads, 4x4 per thread.
// ---------------------------------------------------------------------------
__global__ void qkv_gemm(const float* __restrict__ W, const float* __restrict__ x,
                         const float* __restrict__ nw, const float* __restrict__ bias) {
    __shared__ float As[16][65];
    __shared__ float Bs[16][65];
    int b  = blockIdx.z;
    int m0 = blockIdx.y << 6;
    int t0 = blockIdx.x << 6;
    int tid = threadIdx.x;
    int ar = tid >> 2,  ac = (tid & 3)  << 2;
    int br = tid >> 4,  bc = (tid & 15) << 2;
    int tm = tid >> 4,  tn = tid & 15;
    const float* xb = x + (size_t)b * CH * T;
    float4 ir4 = *(const float4*)&g_ir[b * T + t0 + bc];
    float acc[4][4] = {};

    for (int k0 = 0; k0 < CH; k0 += 16) {
        float4 a4 = *(const float4*)&W[(size_t)(m0 + ar) * CH + k0 + ac];
        As[ac + 0][ar] = a4.x; As[ac + 1][ar] = a4.y;
        As[ac + 2][ar] = a4.z; As[ac + 3][ar] = a4.w;
        float nv = nw[k0 + br];
        float4 b4 = *(const float4*)&xb[(size_t)(k0 + br) * T + t0 + bc];
        Bs[br][bc + 0] = b4.x * nv * ir4.x;
        Bs[br][bc + 1] = b4.y * nv * ir4.y;
        Bs[br][bc + 2] = b4.z * nv * ir4.z;
        Bs[br][bc + 3] = b4.w * nv * ir4.w;
        __syncthreads();
#pragma unroll
        for (int k = 0; k < 16; k++) {
            float av[4], bv[4];
#pragma unroll
            for (int i = 0; i < 4; i++) av[i] = As[k][(tm << 2) + i];
#pragma unroll
            for (int j = 0; j < 4; j++) bv[j] = Bs[k][(tn << 2) + j];
#pragma unroll
            for (int i = 0; i < 4; i++)
#pragma unroll
                for (int j = 0; j < 4; j++)
                    acc[i][j] = fmaf(av[i], bv[j], acc[i][j]);
        }
        __syncthreads();
    }
#pragma unroll
    for (int i = 0; i < 4; i++) {
        int row = m0 + (tm << 2) + i;
        float bi = bias[row];
        float* op = &g_qkv[((size_t)b * M3 + row) * T + t0 + (tn << 2)];
#pragma unroll
        for (int j = 0; j < 4; j++) op[j] = acc[i][j] + bi;
    }
}

// ---------------------------------------------------------------------------
// Kernel 3: flash attention. One block = (head, 64-query tile).
// ch = 64. Q preloaded & pre-scaled by ch^-0.5. P overlays K's smem tile.
// ---------------------------------------------------------------------------
__global__ void attn_kernel() {
    extern __shared__ float sm[];
    float* Qs  = sm;                 // [64][65]  (c, t)
    float* KPs = sm + 64 * 65;       // [64][65]  K:(c,s) then P:(t,s)
    float* Vs  = sm + 2 * 64 * 65;   // [64][65]  (c, s)
    __shared__ float m_run[64], l_run[64], corr_s[64];

    int t0   = blockIdx.x << 6;
    int head = blockIdx.y;           // 0..15
    int b  = head >> 3;
    int hh = head & 7;
    const float* qb = g_qkv + ((size_t)b * M3 + hh * 192) * T;
    const float* kb = qb + (size_t)64 * T;
    const float* vb = qb + (size_t)128 * T;

    int tid = threadIdx.x;
    int tm = tid >> 4, tn = tid & 15;

    // load Q tile, pre-multiplied by scale^2 = ch^-0.5 = 0.125
#pragma unroll
    for (int i = 0; i < 16; i++) {
        int idx = tid + (i << 8);
        int c = idx >> 6, tt = idx & 63;
        Qs[c * 65 + tt] = qb[(size_t)c * T + t0 + tt] * 0.125f;
    }
    if (tid < 64) { m_run[tid] = -1e30f; l_run[tid] = 0.f; }

    float o[4][4] = {};

    for (int s0 = 0; s0 < T; s0 += 64) {
        __syncthreads();   // previous iteration's PV done before overwriting K/V
#pragma unroll
        for (int i = 0; i < 16; i++) {
            int idx = tid + (i << 8);
            int c = idx >> 6, ss = idx & 63;
            KPs[c * 65 + ss] = kb[(size_t)c * T + s0 + ss];
            Vs [c * 65 + ss] = vb[(size_t)c * T + s0 + ss];
        }
        __syncthreads();

        // S = (Q^T K) tile; thread owns rows t=4tm.., cols s=4tn..
        float acc[4][4] = {};
#pragma unroll 8
        for (int c = 0; c < 64; c++) {
            float av[4], bv[4];
#pragma unroll
            for (int i = 0; i < 4; i++) av[i] = Qs[c * 65 + (tm << 2) + i];
#pragma unroll
            for (int j = 0; j < 4; j++) bv[j] = KPs[c * 65 + (tn << 2) + j];
#pragma unroll
            for (int i = 0; i < 4; i++)
#pragma unroll
                for (int j = 0; j < 4; j++)
                    acc[i][j] = fmaf(av[i], bv[j], acc[i][j]);
        }
        __syncthreads();   // everyone done reading K before P overlays it

        // online softmax per row; rows of one tm-group live in one 16-lane group
#pragma unroll
        for (int i = 0; i < 4; i++) {
            int row = (tm << 2) + i;
            float mx = fmaxf(fmaxf(acc[i][0], acc[i][1]), fmaxf(acc[i][2], acc[i][3]));
#pragma unroll
            for (int off = 8; off; off >>= 1)
                mx = fmaxf(mx, __shfl_xor_sync(0xffffffffu, mx, off));
            float m_old = m_run[row];
            float m_new = fmaxf(m_old, mx);
            float p[4], rs = 0.f;
#pragma unroll
            for (int j = 0; j < 4; j++) { p[j] = __expf(acc[i][j] - m_new); rs += p[j]; }
#pragma unroll
            for (int off = 8; off; off >>= 1)
                rs += __shfl_xor_sync(0xffffffffu, rs, off);
            if (tn == 0) {
                float cr = __expf(m_old - m_new);
                corr_s[row] = cr;
                l_run[row] = l_run[row] * cr + rs;
                m_run[row] = m_new;
            }
#pragma unroll
            for (int j = 0; j < 4; j++)
                KPs[row * 65 + (tn << 2) + j] = p[j];   // P[t][s]
        }
        __syncthreads();

        // rescale O and accumulate O[c,t] += sum_s P[t,s] V[c,s]
        // thread owns c=4tm.., t=4tn..
        float cj[4];
#pragma unroll
        for (int j = 0; j < 4; j++) cj[j] = corr_s[(tn << 2) + j];
#pragma unroll
        for (int i = 0; i < 4; i++)
#pragma unroll
            for (int j = 0; j < 4; j++) o[i][j] *= cj[j];

#pragma unroll 8
        for (int s = 0; s < 64; s++) {
            float vv[4], pp[4];
#pragma unroll
            for (int i = 0; i < 4; i++) vv[i] = Vs[((tm << 2) + i) * 65 + s];
#pragma unroll
            for (int j = 0; j < 4; j++) pp[j] = KPs[((tn << 2) + j) * 65 + s];
#pragma unroll
            for (int i = 0; i < 4; i++)
#pragma unroll
                for (int j = 0; j < 4; j++)
                    o[i][j] = fmaf(vv[i], pp[j], o[i][j]);
        }
    }
    __syncthreads();

    float linv[4];
#pragma unroll
    for (int j = 0; j < 4; j++) linv[j] = 1.f / l_run[(tn << 2) + j];

    float* ab = g_a + ((size_t)b * CH + hh * 64) * T;
#pragma unroll
    for (int i = 0; i < 4; i++)
#pragma unroll
        for (int j = 0; j < 4; j++)
            ab[(size_t)((tm << 2) + i) * T + t0 + (tn << 2) + j] = o[i][j] * linv[j];
}

// ---------------------------------------------------------------------------
// Kernel 4: proj GEMM + bias + residual
// ---------------------------------------------------------------------------
__global__ void proj_gemm(const float* __restrict__ W, const float* __restrict__ bias,
                          const float* __restrict__ xres, float* __restrict__ out) {
    __shared__ float As[16][65];
    __shared__ float Bs[16][65];
    int b  = blockIdx.z;
    int m0 = blockIdx.y << 6;
    int t0 = blockIdx.x << 6;
    int tid = threadIdx.x;
    int ar = tid >> 2,  ac = (tid & 3)  << 2;
    int br = tid >> 4,  bc = (tid & 15) << 2;
    int tm = tid >> 4,  tn = tid & 15;
    const float* Ab = g_a + (size_t)b * CH * T;
    float acc[4][4] = {};

    for (int k0 = 0; k0 < CH; k0 += 16) {
        float4 a4 = *(const float4*)&W[(size_t)(m0 + ar) * CH + k0 + ac];
        As[ac + 0][ar] = a4.x; As[ac + 1][ar] = a4.y;
        As[ac + 2][ar] = a4.z; As[ac + 3][ar] = a4.w;
        float4 b4 = *(const float4*)&Ab[(size_t)(k0 + br) * T + t0 + bc];
        Bs[br][bc + 0] = b4.x; Bs[br][bc + 1] = b4.y;
        Bs[br][bc + 2] = b4.z; Bs[br][bc + 3] = b4.w;
        __syncthreads();
#pragma unroll
        for (int k = 0; k < 16; k++) {
            float av[4], bv[4];
#pragma unroll
            for (int i = 0; i < 4; i++) av[i] = As[k][(tm << 2) + i];
#pragma unroll
            for (int j = 0; j < 4; j++) bv[j] = Bs[k][(tn << 2) + j];
#pragma unroll
            for (int i = 0; i < 4; i++)
#pragma unroll
                for (int j = 0; j < 4; j++)
                    acc[i][j] = fmaf(av[i], bv[j], acc[i][j]);
        }
        __syncthreads();
    }
#pragma unroll
    for (int i = 0; i < 4; i++) {
        int row = m0 + (tm << 2) + i;
        float bi = bias[row];
        size_t base = ((size_t)b * CH + row) * T + t0 + (tn << 2);
#pragma unroll
        for (int j = 0; j < 4; j++)
            out[base + j] = acc[i][j] + bi + xres[base + j];
    }
}

// ---------------------------------------------------------------------------
extern "C" void kernel_launch(void* const* d_in, const int* in_sizes, int n_in,
                              void* d_out, int out_size) {
    const float* x      = (const float*)d_in[0];
    const float* nw     = (const float*)d_in[1];
    const float* qkv_w  = (const float*)d_in[2];
    const float* qkv_b  = (const float*)d_in[3];
    const float* proj_w = (const float*)d_in[4];
    const float* proj_b = (const float*)d_in[5];
    float* out = (float*)d_out;

    rms_kernel<<<32, 256>>>(x);
    qkv_gemm<<<dim3(64, 24, 2), 256>>>(qkv_w, x, nw, qkv_b);

    const int ATT_SMEM = 3 * 64 * 65 * (int)sizeof(float);   // 49920 B
    cudaFuncSetAttribute(attn_kernel, cudaFuncAttributeMaxDynamicSharedMemorySize, ATT_SMEM);
    attn_kernel<<<dim3(64, 16), 256, ATT_SMEM>>>();

    proj_gemm<<<dim3(64, 8, 2), 256>>>(proj_w, proj_b, x, out);
}

// round 3
// speedup vs baseline: 1.9919x; 1.8872x over previous
#include <cuda_runtime.h>
#include <math.h>

#define T   4096
#define CHN 512
#define M3  1536

__device__ float g_qkv[(size_t)2 * M3 * T];
__device__ float g_a[(size_t)2 * CHN * T];
__device__ float g_ir[(size_t)2 * T];

__device__ __forceinline__ unsigned tf32r(float x) {
    unsigned r; asm("cvt.rna.tf32.f32 %0, %1;" : "=r"(r) : "f"(x)); return r;
}
__device__ __forceinline__ void mma8(float c[4], const unsigned a[4],
                                     unsigned b0, unsigned b1) {
    asm volatile("mma.sync.aligned.m16n8k8.row.col.f32.tf32.tf32.f32 "
                 "{%0,%1,%2,%3}, {%4,%5,%6,%7}, {%8,%9}, {%0,%1,%2,%3};"
                 : "+f"(c[0]), "+f"(c[1]), "+f"(c[2]), "+f"(c[3])
                 : "r"(a[0]), "r"(a[1]), "r"(a[2]), "r"(a[3]), "r"(b0), "r"(b1));
}

__global__ void rms_kernel(const float* __restrict__ x) {
    int i = blockIdx.x * blockDim.x + threadIdx.x;
    int b = i >> 12, t = i & (T - 1);
    const float* xp = x + (size_t)b * CHN * T + t;
    float s = 0.f;
#pragma unroll 8
    for (int c = 0; c < CHN; c++) { float v = xp[(size_t)c * T]; s = fmaf(v, v, s); }
    g_ir[i] = 22.62741699796952f * rsqrtf(s * (1.0f / CHN) + 1e-8f);
}

// 128x128 tile, BK=32, 8 warps (warp 32x64). QKV: split tf32. proj: single.
template<bool QKV>
__global__ void __launch_bounds__(256) gemm_mma(
        const float* __restrict__ W, const float* __restrict__ Xin,
        const float* __restrict__ nw, const float* __restrict__ bias,
        const float* __restrict__ resid, float* __restrict__ outp)
{
    extern __shared__ unsigned smg[];
    const int RS = 36;
    unsigned* Ahi = smg;
    unsigned* Alo = QKV ? (Ahi + 128 * RS) : Ahi;
    unsigned* Bhi = Alo + 128 * RS;
    unsigned* Blo = QKV ? (Bhi + 128 * RS) : Bhi;

    int b = blockIdx.z, m0 = blockIdx.y * 128, t0 = blockIdx.x * 128;
    int tid = threadIdx.x, lane = tid & 31, wid = tid >> 5;
    int wm = wid >> 1, wn = wid & 1, g = lane >> 2, q = lane & 3;
    const float* Xb = (QKV ? Xin : (const float*)g_a) + (size_t)b * CHN * T;
    int bc4 = tid & 7, bt4 = tid >> 3;
    float4 ir4 = make_float4(1.f, 1.f, 1.f, 1.f);
    if (QKV) ir4 = *(const float4*)&g_ir[b * T + t0 + 4 * bt4];

    float acc[2][8][4];
#pragma unroll
    for (int mt = 0; mt < 2; mt++)
#pragma unroll
        for (int nt = 0; nt < 8; nt++)
#pragma unroll
            for (int i = 0; i < 4; i++) acc[mt][nt][i] = 0.f;

    for (int k0 = 0; k0 < CHN; k0 += 32) {
#pragma unroll
        for (int i = 0; i < 4; i++) {
            int idx = tid + i * 256, row = idx >> 3, c4 = idx & 7;
            float4 w = *(const float4*)&W[(size_t)(m0 + row) * CHN + k0 + 4 * c4];
            unsigned h0 = tf32r(w.x), h1 = tf32r(w.y), h2 = tf32r(w.z), h3 = tf32r(w.w);
            *(uint4*)&Ahi[row * RS + 4 * c4] = make_uint4(h0, h1, h2, h3);
            if (QKV)
                *(uint4*)&Alo[row * RS + 4 * c4] = make_uint4(
                    tf32r(w.x - __uint_as_float(h0)), tf32r(w.y - __uint_as_float(h1)),
                    tf32r(w.z - __uint_as_float(h2)), tf32r(w.w - __uint_as_float(h3)));
        }
        {
            float4 r[4];
#pragma unroll
            for (int j = 0; j < 4; j++) {
                r[j] = *(const float4*)&Xb[(size_t)(k0 + 4 * bc4 + j) * T + t0 + 4 * bt4];
                if (QKV) {
                    float s = nw[k0 + 4 * bc4 + j];
                    r[j].x *= s * ir4.x; r[j].y *= s * ir4.y;
                    r[j].z *= s * ir4.z; r[j].w *= s * ir4.w;
                }
            }
#pragma unroll
            for (int jp = 0; jp < 4; jp++) {
                float v0 = (&r[0].x)[jp], v1 = (&r[1].x)[jp];
                float v2 = (&r[2].x)[jp], v3 = (&r[3].x)[jp];
                unsigned h0 = tf32r(v0), h1 = tf32r(v1), h2 = tf32r(v2), h3 = tf32r(v3);
                *(uint4*)&Bhi[(4 * bt4 + jp) * RS + 4 * bc4] = make_uint4(h0, h1, h2, h3);
                if (QKV)
                    *(uint4*)&Blo[(4 * bt4 + jp) * RS + 4 * bc4] = make_uint4(
                        tf32r(v0 - __uint_as_float(h0)), tf32r(v1 - __uint_as_float(h1)),
                        tf32r(v2 - __uint_as_float(h2)), tf32r(v3 - __uint_as_float(h3)));
            }
        }
        __syncthreads();
#pragma unroll
        for (int ks = 0; ks < 4; ks++) {
            unsigned ah[2][4], al[2][4];
#pragma unroll
            for (int mt = 0; mt < 2; mt++) {
                int rb = wm * 32 + mt * 16;
                ah[mt][0] = Ahi[(rb + g) * RS + ks * 8 + q];
                ah[mt][1] = Ahi[(rb + g + 8) * RS + ks * 8 + q];
                ah[mt][2] = Ahi[(rb + g) * RS + ks * 8 + q + 4];
                ah[mt][3] = Ahi[(rb + g + 8) * RS + ks * 8 + q + 4];
                if (QKV) {
                    al[mt][0] = Alo[(rb + g) * RS + ks * 8 + q];
                    al[mt][1] = Alo[(rb + g + 8) * RS + ks * 8 + q];
                    al[mt][2] = Alo[(rb + g) * RS + ks * 8 + q + 4];
                    al[mt][3] = Alo[(rb + g + 8) * RS + ks * 8 + q + 4];
                }
            }
#pragma unroll
            for (int nt = 0; nt < 8; nt++) {
                int cb = wn * 64 + nt * 8;
                unsigned bh0 = Bhi[(cb + g) * RS + ks * 8 + q];
                unsigned bh1 = Bhi[(cb + g) * RS + ks * 8 + q + 4];
#pragma unroll
                for (int mt = 0; mt < 2; mt++) mma8(acc[mt][nt], ah[mt], bh0, bh1);
                if (QKV) {
                    unsigned bl0 = Blo[(cb + g) * RS + ks * 8 + q];
                    unsigned bl1 = Blo[(cb + g) * RS + ks * 8 + q + 4];
#pragma unroll
                    for (int mt = 0; mt < 2; mt++) {
                        mma8(acc[mt][nt], ah[mt], bl0, bl1);
                        mma8(acc[mt][nt], al[mt], bh0, bh1);
                    }
                }
            }
        }
        __syncthreads();
    }
#pragma unroll
    for (int mt = 0; mt < 2; mt++) {
        int row = m0 + wm * 32 + mt * 16 + g;
        float bi0 = bias[row], bi1 = bias[row + 8];
#pragma unroll
        for (int nt = 0; nt < 8; nt++) {
            int col = t0 + wn * 64 + nt * 8 + 2 * q;
            if (QKV) {
                *(float2*)&g_qkv[((size_t)b * M3 + row) * T + col] =
                    make_float2(acc[mt][nt][0] + bi0, acc[mt][nt][1] + bi0);
                *(float2*)&g_qkv[((size_t)b * M3 + row + 8) * T + col] =
                    make_float2(acc[mt][nt][2] + bi1, acc[mt][nt][3] + bi1);
            } else {
                size_t i0 = ((size_t)b * CHN + row) * T + col;
                size_t i1 = ((size_t)b * CHN + row + 8) * T + col;
                float2 r0 = *(const float2*)&resid[i0];
                float2 r1 = *(const float2*)&resid[i1];
                *(float2*)&outp[i0] = make_float2(acc[mt][nt][0] + bi0 + r0.x,
                                                  acc[mt][nt][1] + bi0 + r0.y);
                *(float2*)&outp[i1] = make_float2(acc[mt][nt][2] + bi1 + r1.x,
                                                  acc[mt][nt][3] + bi1 + r1.y);
            }
        }
    }
}

// Flash attention: block = 128 queries x 1 head, 8 warps x 16 rows.
// QK^T split tf32, PV single tf32. Ps overlays Qhi after frag load.
__global__ void __launch_bounds__(256) attn_mma() {
    extern __shared__ unsigned sma[];
    unsigned* Ps  = sma;              // [128][68] (= Qhi in prologue)
    unsigned* Qlo = sma + 8704;       // prologue only
    unsigned* Khi = sma + 8704;       // [64][68]
    unsigned* Klo = sma + 13056;      // [64][68]
    unsigned* Vs  = sma + 17408;      // [64][68]

    int t0 = blockIdx.x * 128, head = blockIdx.y;
    int b = head >> 3, hh = head & 7;
    const float* qb = g_qkv + ((size_t)b * M3 + hh * 192) * T;
    const float* kb = qb + (size_t)64 * T;
    const float* vb = qb + (size_t)128 * T;
    int tid = threadIdx.x, lane = tid & 31, wid = tid >> 5;
    int g = lane >> 2, q = lane & 3, rb = wid * 16;

    {   // Q fill: [c][t] -> [t][c] * 0.125, split
        int c4 = tid & 15;
#pragma unroll
        for (int it = 0; it < 2; it++) {
            int t4 = (tid >> 4) + it * 16;
            float4 r[4];
#pragma unroll
            for (int j = 0; j < 4; j++) {
                r[j] = *(const float4*)&qb[(size_t)(4 * c4 + j) * T + t0 + 4 * t4];
                r[j].x *= 0.125f; r[j].y *= 0.125f; r[j].z *= 0.125f; r[j].w *= 0.125f;
            }
#pragma unroll
            for (int jp = 0; jp < 4; jp++) {
                float v0 = (&r[0].x)[jp], v1 = (&r[1].x)[jp];
                float v2 = (&r[2].x)[jp], v3 = (&r[3].x)[jp];
                unsigned h0 = tf32r(v0), h1 = tf32r(v1), h2 = tf32r(v2), h3 = tf32r(v3);
                *(uint4*)&Ps[(4 * t4 + jp) * 68 + 4 * c4] = make_uint4(h0, h1, h2, h3);
                *(uint4*)&Qlo[(4 * t4 + jp) * 68 + 4 * c4] = make_uint4(
                    tf32r(v0 - __uint_as_float(h0)), tf32r(v1 - __uint_as_float(h1)),
                    tf32r(v2 - __uint_as_float(h2)), tf32r(v3 - __uint_as_float(h3)));
            }
        }
    }
    __syncthreads();
    unsigned qh[8][4], ql[8][4];
#pragma unroll
    for (int ks = 0; ks < 8; ks++) {
        qh[ks][0] = Ps[(rb + g) * 68 + ks * 8 + q];
        qh[ks][1] = Ps[(rb + g + 8) * 68 + ks * 8 + q];
        qh[ks][2] = Ps[(rb + g) * 68 + ks * 8 + q + 4];
        qh[ks][3] = Ps[(rb + g + 8) * 68 + ks * 8 + q + 4];
        ql[ks][0] = Qlo[(rb + g) * 68 + ks * 8 + q];
        ql[ks][1] = Qlo[(rb + g + 8) * 68 + ks * 8 + q];
        ql[ks][2] = Qlo[(rb + g) * 68 + ks * 8 + q + 4];
        ql[ks][3] = Qlo[(rb + g + 8) * 68 + ks * 8 + q + 4];
    }

    float o[8][4];
#pragma unroll
    for (int nt = 0; nt < 8; nt++)
#pragma unroll
        for (int i = 0; i < 4; i++) o[nt][i] = 0.f;
    float m_a = -1e30f, m_b = -1e30f, l_a = 0.f, l_b = 0.f;

    for (int s0 = 0; s0 < T; s0 += 64) {
        __syncthreads();
        {   // K fill (split) + V fill (single)
            int c4 = tid & 15, s4 = tid >> 4;
            float4 r[4];
#pragma unroll
            for (int j = 0; j < 4; j++)
                r[j] = *(const float4*)&kb[(size_t)(4 * c4 + j) * T + s0 + 4 * s4];
#pragma unroll
            for (int jp = 0; jp < 4; jp++) {
                float v0 = (&r[0].x)[jp], v1 = (&r[1].x)[jp];
                float v2 = (&r[2].x)[jp], v3 = (&r[3].x)[jp];
                unsigned h0 = tf32r(v0), h1 = tf32r(v1), h2 = tf32r(v2), h3 = tf32r(v3);
                *(uint4*)&Khi[(4 * s4 + jp) * 68 + 4 * c4] = make_uint4(h0, h1, h2, h3);
                *(uint4*)&Klo[(4 * s4 + jp) * 68 + 4 * c4] = make_uint4(
                    tf32r(v0 - __uint_as_float(h0)), tf32r(v1 - __uint_as_float(h1)),
                    tf32r(v2 - __uint_as_float(h2)), tf32r(v3 - __uint_as_float(h3)));
            }
#pragma unroll
            for (int i = 0; i < 4; i++) {
                int idx = tid + i * 256, c = idx >> 4, sv = idx & 15;
                float4 v = *(const float4*)&vb[(size_t)c * T + s0 + 4 * sv];
                *(uint4*)&Vs[c * 68 + 4 * sv] =
                    make_uint4(tf32r(v.x), tf32r(v.y), tf32r(v.z), tf32r(v.w));
            }
        }
        __syncthreads();

        float sacc[8][4];
#pragma unroll
        for (int nt = 0; nt < 8; nt++)
#pragma unroll
            for (int i = 0; i < 4; i++) sacc[nt][i] = 0.f;
#pragma unroll
        for (int ks = 0; ks < 8; ks++)
#pragma unroll
            for (int nt = 0; nt < 8; nt++) {
                unsigned bh0 = Khi[(nt * 8 + g) * 68 + ks * 8 + q];
                unsigned bh1 = Khi[(nt * 8 + g) * 68 + ks * 8 + q + 4];
                unsigned bl0 = Klo[(nt * 8 + g) * 68 + ks * 8 + q];
                unsigned bl1 = Klo[(nt * 8 + g) * 68 + ks * 8 + q + 4];
                mma8(sacc[nt], qh[ks], bh0, bh1);
                mma8(sacc[nt], qh[ks], bl0, bl1);
                mma8(sacc[nt], ql[ks], bh0, bh1);
            }

        float mx_a = -1e30f, mx_b = -1e30f;
#pragma unroll
        for (int nt = 0; nt < 8; nt++) {
            mx_a = fmaxf(mx_a, fmaxf(sacc[nt][0], sacc[nt][1]));
            mx_b = fmaxf(mx_b, fmaxf(sacc[nt][2], sacc[nt][3]));
        }
        mx_a = fmaxf(mx_a, __shfl_xor_sync(~0u, mx_a, 1));
        mx_a = fmaxf(mx_a, __shfl_xor_sync(~0u, mx_a, 2));
        mx_b = fmaxf(mx_b, __shfl_xor_sync(~0u, mx_b, 1));
        mx_b = fmaxf(mx_b, __shfl_xor_sync(~0u, mx_b, 2));
        float mn_a = fmaxf(m_a, mx_a), mn_b = fmaxf(m_b, mx_b);
        float ca = __expf(m_a - mn_a), cb = __expf(m_b - mn_b);
        float sum_a = 0.f, sum_b = 0.f;
#pragma unroll
        for (int nt = 0; nt < 8; nt++) {
            float p0 = __expf(sacc[nt][0] - mn_a), p1 = __expf(sacc[nt][1] - mn_a);
            float p2 = __expf(sacc[nt][2] - mn_b), p3 = __expf(sacc[nt][3] - mn_b);
            sum_a += p0 + p1; sum_b += p2 + p3;
            *(uint2*)&Ps[(rb + g) * 68 + nt * 8 + 2 * q] = make_uint2(tf32r(p0), tf32r(p1));
            *(uint2*)&Ps[(rb + g + 8) * 68 + nt * 8 + 2 * q] = make_uint2(tf32r(p2), tf32r(p3));
        }
        sum_a += __shfl_xor_sync(~0u, sum_a, 1);
        sum_a += __shfl_xor_sync(~0u, sum_a, 2);
        sum_b += __shfl_xor_sync(~0u, sum_b, 1);
        sum_b += __shfl_xor_sync(~0u, sum_b, 2);
        m_a = mn_a; m_b = mn_b;
        l_a = l_a * ca + sum_a; l_b = l_b * cb + sum_b;
#pragma unroll
        for (int nt = 0; nt < 8; nt++) {
            o[nt][0] *= ca; o[nt][1] *= ca; o[nt][2] *= cb; o[nt][3] *= cb;
        }
        __syncwarp();
#pragma unroll
        for (int ks = 0; ks < 8; ks++) {
            unsigned ph[4];
            ph[0] = Ps[(rb + g) * 68 + ks * 8 + q];
            ph[1] = Ps[(rb + g + 8) * 68 + ks * 8 + q];
            ph[2] = Ps[(rb + g) * 68 + ks * 8 + q + 4];
            ph[3] = Ps[(rb + g + 8) * 68 + ks * 8 + q + 4];
#pragma unroll
            for (int nt = 0; nt < 8; nt++) {
                unsigned bv0 = Vs[(nt * 8 + g) * 68 + ks * 8 + q];
                unsigned bv1 = Vs[(nt * 8 + g) * 68 + ks * 8 + q + 4];
                mma8(o[nt], ph, bv0, bv1);
            }
        }
    }

    float inv_a = 1.f / l_a, inv_b = 1.f / l_b;
    float* ab = g_a + ((size_t)b * CHN + hh * 64) * T;
#pragma unroll
    for (int nt = 0; nt < 8; nt++) {
        int c0 = nt * 8 + 2 * q;
        ab[(size_t)c0 * T + t0 + rb + g]           = o[nt][0] * inv_a;
        ab[(size_t)(c0 + 1) * T + t0 + rb + g]     = o[nt][1] * inv_a;
        ab[(size_t)c0 * T + t0 + rb + g + 8]       = o[nt][2] * inv_b;
        ab[(size_t)(c0 + 1) * T + t0 + rb + g + 8] = o[nt][3] * inv_b;
    }
}

extern "C" void kernel_launch(void* const* d_in, const int* in_sizes, int n_in,
                              void* d_out, int out_size) {
    const float* x      = (const float*)d_in[0];
    const float* nw     = (const float*)d_in[1];
    const float* qkv_w  = (const float*)d_in[2];
    const float* qkv_b  = (const float*)d_in[3];
    const float* proj_w = (const float*)d_in[4];
    const float* proj_b = (const float*)d_in[5];
    float* out = (float*)d_out;

    const int QKV_SMEM  = 4 * 128 * 36 * 4;   // 73728
    const int PROJ_SMEM = 2 * 128 * 36 * 4;   // 36864
    const int ATT_SMEM  = 21760 * 4;          // 87040
    static bool init = false;
    if (!init) {
        cudaFuncSetAttribute(gemm_mma<true>,  cudaFuncAttributeMaxDynamicSharedMemorySize, QKV_SMEM);
        cudaFuncSetAttribute(gemm_mma<false>, cudaFuncAttributeMaxDynamicSharedMemorySize, PROJ_SMEM);
        cudaFuncSetAttribute(attn_mma,        cudaFuncAttributeMaxDynamicSharedMemorySize, ATT_SMEM);
        init = true;
    }
    rms_kernel<<<32, 256>>>(x);
    gemm_mma<true><<<dim3(32, 12, 2), 256, QKV_SMEM>>>(qkv_w, x, nw, qkv_b, nullptr, nullptr);
    attn_mma<<<dim3(32, 16), 256, ATT_SMEM>>>();
    gemm_mma<false><<<dim3(32, 4, 2), 256, PROJ_SMEM>>>(proj_w, nullptr, nullptr, proj_b, x, out);
}

// round 4
// speedup vs baseline: 1.9934x; 1.0008x over previous
#include <cuda_runtime.h>
#include <math.h>

#define T   4096
#define CHN 512
#define M3  1536

__device__ float g_qkv[(size_t)2 * M3 * T];
__device__ float g_a[(size_t)2 * CHN * T];
__device__ float g_ir[(size_t)2 * T];

__device__ __forceinline__ unsigned tf32r(float x) {
    unsigned r; asm("cvt.rna.tf32.f32 %0, %1;" : "=r"(r) : "f"(x)); return r;
}
__device__ __forceinline__ void mma8(float c[4], const unsigned a[4],
                                     unsigned b0, unsigned b1) {
    asm volatile("mma.sync.aligned.m16n8k8.row.col.f32.tf32.tf32.f32 "
                 "{%0,%1,%2,%3}, {%4,%5,%6,%7}, {%8,%9}, {%0,%1,%2,%3};"
                 : "+f"(c[0]), "+f"(c[1]), "+f"(c[2]), "+f"(c[3])
                 : "r"(a[0]), "r"(a[1]), "r"(a[2]), "r"(a[3]), "r"(b0), "r"(b1));
}

__global__ void rms_kernel(const float* __restrict__ x) {
    int i = blockIdx.x * blockDim.x + threadIdx.x;
    int b = i >> 12, t = i & (T - 1);
    const float* xp = x + (size_t)b * CHN * T + t;
    float s = 0.f;
#pragma unroll 8
    for (int c = 0; c < CHN; c++) { float v = xp[(size_t)c * T]; s = fmaf(v, v, s); }
    g_ir[i] = 22.62741699796952f * rsqrtf(s * (1.0f / CHN) + 1e-8f);
}

// 128x128 tile, BK=32, 8 warps (warp 32x64). QKV: split tf32. proj: single.
template<bool QKV>
__global__ void __launch_bounds__(256) gemm_mma(
        const float* __restrict__ W, const float* __restrict__ Xin,
        const float* __restrict__ nw, const float* __restrict__ bias,
        const float* __restrict__ resid, float* __restrict__ outp)
{
    extern __shared__ unsigned smg[];
    const int RS = 36;
    unsigned* Ahi = smg;
    unsigned* Alo = QKV ? (Ahi + 128 * RS) : Ahi;
    unsigned* Bhi = Alo + 128 * RS;
    unsigned* Blo = QKV ? (Bhi + 128 * RS) : Bhi;

    int b = blockIdx.z, m0 = blockIdx.y * 128, t0 = blockIdx.x * 128;
    int tid = threadIdx.x, lane = tid & 31, wid = tid >> 5;
    int wm = wid >> 1, wn = wid & 1, g = lane >> 2, q = lane & 3;
    const float* Xb = (QKV ? Xin : (const float*)g_a) + (size_t)b * CHN * T;
    int bc4 = tid & 7, bt4 = tid >> 3;
    float4 ir4 = make_float4(1.f, 1.f, 1.f, 1.f);
    if (QKV) ir4 = *(const float4*)&g_ir[b * T + t0 + 4 * bt4];

    float acc[2][8][4];
#pragma unroll
    for (int mt = 0; mt < 2; mt++)
#pragma unroll
        for (int nt = 0; nt < 8; nt++)
#pragma unroll
            for (int i = 0; i < 4; i++) acc[mt][nt][i] = 0.f;

    for (int k0 = 0; k0 < CHN; k0 += 32) {
#pragma unroll
        for (int i = 0; i < 4; i++) {
            int idx = tid + i * 256, row = idx >> 3, c4 = idx & 7;
            float4 w = *(const float4*)&W[(size_t)(m0 + row) * CHN + k0 + 4 * c4];
            unsigned h0 = tf32r(w.x), h1 = tf32r(w.y), h2 = tf32r(w.z), h3 = tf32r(w.w);
            *(uint4*)&Ahi[row * RS + 4 * c4] = make_uint4(h0, h1, h2, h3);
            if (QKV)
                *(uint4*)&Alo[row * RS + 4 * c4] = make_uint4(
                    tf32r(w.x - __uint_as_float(h0)), tf32r(w.y - __uint_as_float(h1)),
                    tf32r(w.z - __uint_as_float(h2)), tf32r(w.w - __uint_as_float(h3)));
        }
        {
            float4 r[4];
#pragma unroll
            for (int j = 0; j < 4; j++) {
                r[j] = *(const float4*)&Xb[(size_t)(k0 + 4 * bc4 + j) * T + t0 + 4 * bt4];
                if (QKV) {
                    float s = nw[k0 + 4 * bc4 + j];
                    r[j].x *= s * ir4.x; r[j].y *= s * ir4.y;
                    r[j].z *= s * ir4.z; r[j].w *= s * ir4.w;
                }
            }
#pragma unroll
            for (int jp = 0; jp < 4; jp++) {
                float v0 = (&r[0].x)[jp], v1 = (&r[1].x)[jp];
                float v2 = (&r[2].x)[jp], v3 = (&r[3].x)[jp];
                unsigned h0 = tf32r(v0), h1 = tf32r(v1), h2 = tf32r(v2), h3 = tf32r(v3);
                *(uint4*)&Bhi[(4 * bt4 + jp) * RS + 4 * bc4] = make_uint4(h0, h1, h2, h3);
                if (QKV)
                    *(uint4*)&Blo[(4 * bt4 + jp) * RS + 4 * bc4] = make_uint4(
                        tf32r(v0 - __uint_as_float(h0)), tf32r(v1 - __uint_as_float(h1)),
                        tf32r(v2 - __uint_as_float(h2)), tf32r(v3 - __uint_as_float(h3)));
            }
        }
        __syncthreads();
#pragma unroll
        for (int ks = 0; ks < 4; ks++) {
            unsigned ah[2][4], al[2][4];
#pragma unroll
            for (int mt = 0; mt < 2; mt++) {
                int rb = wm * 32 + mt * 16;
                ah[mt][0] = Ahi[(rb + g) * RS + ks * 8 + q];
                ah[mt][1] = Ahi[(rb + g + 8) * RS + ks * 8 + q];
                ah[mt][2] = Ahi[(rb + g) * RS + ks * 8 + q + 4];
                ah[mt][3] = Ahi[(rb + g + 8) * RS + ks * 8 + q + 4];
                if (QKV) {
                    al[mt][0] = Alo[(rb + g) * RS + ks * 8 + q];
                    al[mt][1] = Alo[(rb + g + 8) * RS + ks * 8 + q];
                    al[mt][2] = Alo[(rb + g) * RS + ks * 8 + q + 4];
                    al[mt][3] = Alo[(rb + g + 8) * RS + ks * 8 + q + 4];
                }
            }
#pragma unroll
            for (int nt = 0; nt < 8; nt++) {
                int cb = wn * 64 + nt * 8;
                unsigned bh0 = Bhi[(cb + g) * RS + ks * 8 + q];
                unsigned bh1 = Bhi[(cb + g) * RS + ks * 8 + q + 4];
#pragma unroll
                for (int mt = 0; mt < 2; mt++) mma8(acc[mt][nt], ah[mt], bh0, bh1);
                if (QKV) {
                    unsigned bl0 = Blo[(cb + g) * RS + ks * 8 + q];
                    unsigned bl1 = Blo[(cb + g) * RS + ks * 8 + q + 4];
#pragma unroll
                    for (int mt = 0; mt < 2; mt++) {
                        mma8(acc[mt][nt], ah[mt], bl0, bl1);
                        mma8(acc[mt][nt], al[mt], bh0, bh1);
                    }
                }
            }
        }
        __syncthreads();
    }
#pragma unroll
    for (int mt = 0; mt < 2; mt++) {
        int row = m0 + wm * 32 + mt * 16 + g;
        float bi0 = bias[row], bi1 = bias[row + 8];
#pragma unroll
        for (int nt = 0; nt < 8; nt++) {
            int col = t0 + wn * 64 + nt * 8 + 2 * q;
            if (QKV) {
                *(float2*)&g_qkv[((size_t)b * M3 + row) * T + col] =
                    make_float2(acc[mt][nt][0] + bi0, acc[mt][nt][1] + bi0);
                *(float2*)&g_qkv[((size_t)b * M3 + row + 8) * T + col] =
                    make_float2(acc[mt][nt][2] + bi1, acc[mt][nt][3] + bi1);
            } else {
                size_t i0 = ((size_t)b * CHN + row) * T + col;
                size_t i1 = ((size_t)b * CHN + row + 8) * T + col;
                float2 r0 = *(const float2*)&resid[i0];
                float2 r1 = *(const float2*)&resid[i1];
                *(float2*)&outp[i0] = make_float2(acc[mt][nt][0] + bi0 + r0.x,
                                                  acc[mt][nt][1] + bi0 + r0.y);
                *(float2*)&outp[i1] = make_float2(acc[mt][nt][2] + bi1 + r1.x,
                                                  acc[mt][nt][3] + bi1 + r1.y);
            }
        }
    }
}

// Flash attention: block = 128 queries x 1 head, 8 warps x 16 rows.
// QK^T split tf32, PV single tf32. Ps overlays Qhi after frag load.
__global__ void __launch_bounds__(256) attn_mma() {
    extern __shared__ unsigned sma[];
    unsigned* Ps  = sma;              // [128][68] (= Qhi in prologue)
    unsigned* Qlo = sma + 8704;       // prologue only
    unsigned* Khi = sma + 8704;       // [64][68]
    unsigned* Klo = sma + 13056;      // [64][68]
    unsigned* Vs  = sma + 17408;      // [64][68]

    int t0 = blockIdx.x * 128, head = blockIdx.y;
    int b = head >> 3, hh = head & 7;
    const float* qb = g_qkv + ((size_t)b * M3 + hh * 192) * T;
    const float* kb = qb + (size_t)64 * T;
    const float* vb = qb + (size_t)128 * T;
    int tid = threadIdx.x, lane = tid & 31, wid = tid >> 5;
    int g = lane >> 2, q = lane & 3, rb = wid * 16;

    {   // Q fill: [c][t] -> [t][c] * 0.125, split
        int c4 = tid & 15;
#pragma unroll
        for (int it = 0; it < 2; it++) {
            int t4 = (tid >> 4) + it * 16;
            float4 r[4];
#pragma unroll
            for (int j = 0; j < 4; j++) {
                r[j] = *(const float4*)&qb[(size_t)(4 * c4 + j) * T + t0 + 4 * t4];
                r[j].x *= 0.125f; r[j].y *= 0.125f; r[j].z *= 0.125f; r[j].w *= 0.125f;
            }
#pragma unroll
            for (int jp = 0; jp < 4; jp++) {
                float v0 = (&r[0].x)[jp], v1 = (&r[1].x)[jp];
                float v2 = (&r[2].x)[jp], v3 = (&r[3].x)[jp];
                unsigned h0 = tf32r(v0), h1 = tf32r(v1), h2 = tf32r(v2), h3 = tf32r(v3);
                *(uint4*)&Ps[(4 * t4 + jp) * 68 + 4 * c4] = make_uint4(h0, h1, h2, h3);
                *(uint4*)&Qlo[(4 * t4 + jp) * 68 + 4 * c4] = make_uint4(
                    tf32r(v0 - __uint_as_float(h0)), tf32r(v1 - __uint_as_float(h1)),
                    tf32r(v2 - __uint_as_float(h2)), tf32r(v3 - __uint_as_float(h3)));
            }
        }
    }
    __syncthreads();
    unsigned qh[8][4], ql[8][4];
#pragma unroll
    for (int ks = 0; ks < 8; ks++) {
        qh[ks][0] = Ps[(rb + g) * 68 + ks * 8 + q];
        qh[ks][1] = Ps[(rb + g + 8) * 68 + ks * 8 + q];
        qh[ks][2] = Ps[(rb + g) * 68 + ks * 8 + q + 4];
        qh[ks][3] = Ps[(rb + g + 8) * 68 + ks * 8 + q + 4];
        ql[ks][0] = Qlo[(rb + g) * 68 + ks * 8 + q];
        ql[ks][1] = Qlo[(rb + g + 8) * 68 + ks * 8 + q];
        ql[ks][2] = Qlo[(rb + g) * 68 + ks * 8 + q + 4];
        ql[ks][3] = Qlo[(rb + g + 8) * 68 + ks * 8 + q + 4];
    }

    float o[8][4];
#pragma unroll
    for (int nt = 0; nt < 8; nt++)
#pragma unroll
        for (int i = 0; i < 4; i++) o[nt][i] = 0.f;
    float m_a = -1e30f, m_b = -1e30f, l_a = 0.f, l_b = 0.f;

    for (int s0 = 0; s0 < T; s0 += 64) {
        __syncthreads();
        {   // K fill (split) + V fill (single)
            int c4 = tid & 15, s4 = tid >> 4;
            float4 r[4];
#pragma unroll
            for (int j = 0; j < 4; j++)
                r[j] = *(const float4*)&kb[(size_t)(4 * c4 + j) * T + s0 + 4 * s4];
#pragma unroll
            for (int jp = 0; jp < 4; jp++) {
                float v0 = (&r[0].x)[jp], v1 = (&r[1].x)[jp];
                float v2 = (&r[2].x)[jp], v3 = (&r[3].x)[jp];
                unsigned h0 = tf32r(v0), h1 = tf32r(v1), h2 = tf32r(v2), h3 = tf32r(v3);
                *(uint4*)&Khi[(4 * s4 + jp) * 68 + 4 * c4] = make_uint4(h0, h1, h2, h3);
                *(uint4*)&Klo[(4 * s4 + jp) * 68 + 4 * c4] = make_uint4(
                    tf32r(v0 - __uint_as_float(h0)), tf32r(v1 - __uint_as_float(h1)),
                    tf32r(v2 - __uint_as_float(h2)), tf32r(v3 - __uint_as_float(h3)));
            }
#pragma unroll
            for (int i = 0; i < 4; i++) {
                int idx = tid + i * 256, c = idx >> 4, sv = idx & 15;
                float4 v = *(const float4*)&vb[(size_t)c * T + s0 + 4 * sv];
                *(uint4*)&Vs[c * 68 + 4 * sv] =
                    make_uint4(tf32r(v.x), tf32r(v.y), tf32r(v.z), tf32r(v.w));
            }
        }
        __syncthreads();

        float sacc[8][4];
#pragma unroll
        for (int nt = 0; nt < 8; nt++)
#pragma unroll
            for (int i = 0; i < 4; i++) sacc[nt][i] = 0.f;
#pragma unroll
        for (int ks = 0; ks < 8; ks++)
#pragma unroll
            for (int nt = 0; nt < 8; nt++) {
                unsigned bh0 = Khi[(nt * 8 + g) * 68 + ks * 8 + q];
                unsigned bh1 = Khi[(nt * 8 + g) * 68 + ks * 8 + q + 4];
                unsigned bl0 = Klo[(nt * 8 + g) * 68 + ks * 8 + q];
                unsigned bl1 = Klo[(nt * 8 + g) * 68 + ks * 8 + q + 4];
                mma8(sacc[nt], qh[ks], bh0, bh1);
                mma8(sacc[nt], qh[ks], bl0, bl1);
                mma8(sacc[nt], ql[ks], bh0, bh1);
            }

        float mx_a = -1e30f, mx_b = -1e30f;
#pragma unroll
        for (int nt = 0; nt < 8; nt++) {
            mx_a = fmaxf(mx_a, fmaxf(sacc[nt][0], sacc[nt][1]));
            mx_b = fmaxf(mx_b, fmaxf(sacc[nt][2], sacc[nt][3]));
        }
        mx_a = fmaxf(mx_a, __shfl_xor_sync(~0u, mx_a, 1));
        mx_a = fmaxf(mx_a, __shfl_xor_sync(~0u, mx_a, 2));
        mx_b = fmaxf(mx_b, __shfl_xor_sync(~0u, mx_b, 1));
        mx_b = fmaxf(mx_b, __shfl_xor_sync(~0u, mx_b, 2));
        float mn_a = fmaxf(m_a, mx_a), mn_b = fmaxf(m_b, mx_b);
        float ca = __expf(m_a - mn_a), cb = __expf(m_b - mn_b);
        float sum_a = 0.f, sum_b = 0.f;
#pragma unroll
        for (int nt = 0; nt < 8; nt++) {
            float p0 = __expf(sacc[nt][0] - mn_a), p1 = __expf(sacc[nt][1] - mn_a);
            float p2 = __expf(sacc[nt][2] - mn_b), p3 = __expf(sacc[nt][3] - mn_b);
            sum_a += p0 + p1; sum_b += p2 + p3;
            *(uint2*)&Ps[(rb + g) * 68 + nt * 8 + 2 * q] = make_uint2(tf32r(p0), tf32r(p1));
            *(uint2*)&Ps[(rb + g + 8) * 68 + nt * 8 + 2 * q] = make_uint2(tf32r(p2), tf32r(p3));
        }
        sum_a += __shfl_xor_sync(~0u, sum_a, 1);
        sum_a += __shfl_xor_sync(~0u, sum_a, 2);
        sum_b += __shfl_xor_sync(~0u, sum_b, 1);
        sum_b += __shfl_xor_sync(~0u, sum_b, 2);
        m_a = mn_a; m_b = mn_b;
        l_a = l_a * ca + sum_a; l_b = l_b * cb + sum_b;
#pragma unroll
        for (int nt = 0; nt < 8; nt++) {
            o[nt][0] *= ca; o[nt][1] *= ca; o[nt][2] *= cb; o[nt][3] *= cb;
        }
        __syncwarp();
#pragma unroll
        for (int ks = 0; ks < 8; ks++) {
            unsigned ph[4];
            ph[0] = Ps[(rb + g) * 68 + ks * 8 + q];
            ph[1] = Ps[(rb + g + 8) * 68 + ks * 8 + q];
            ph[2] = Ps[(rb + g) * 68 + ks * 8 + q + 4];
            ph[3] = Ps[(rb + g + 8) * 68 + ks * 8 + q + 4];
#pragma unroll
            for (int nt = 0; nt < 8; nt++) {
                unsigned bv0 = Vs[(nt * 8 + g) * 68 + ks * 8 + q];
                unsigned bv1 = Vs[(nt * 8 + g) * 68 + ks * 8 + q + 4];
                mma8(o[nt], ph, bv0, bv1);
            }
        }
    }

    float inv_a = 1.f / l_a, inv_b = 1.f / l_b;
    float* ab = g_a + ((size_t)b * CHN + hh * 64) * T;
#pragma unroll
    for (int nt = 0; nt < 8; nt++) {
        int c0 = nt * 8 + 2 * q;
        ab[(size_t)c0 * T + t0 + rb + g]           = o[nt][0] * inv_a;
        ab[(size_t)(c0 + 1) * T + t0 + rb + g]     = o[nt][1] * inv_a;
        ab[(size_t)c0 * T + t0 + rb + g + 8]       = o[nt][2] * inv_b;
        ab[(size_t)(c0 + 1) * T + t0 + rb + g + 8] = o[nt][3] * inv_b;
    }
}

extern "C" void kernel_launch(void* const* d_in, const int* in_sizes, int n_in,
                              void* d_out, int out_size) {
    const float* x      = (const float*)d_in[0];
    const float* nw     = (const float*)d_in[1];
    const float* qkv_w  = (const float*)d_in[2];
    const float* qkv_b  = (const float*)d_in[3];
    const float* proj_w = (const float*)d_in[4];
    const float* proj_b = (const float*)d_in[5];
    float* out = (float*)d_out;

    const int QKV_SMEM  = 4 * 128 * 36 * 4;   // 73728
    const int PROJ_SMEM = 2 * 128 * 36 * 4;   // 36864
    const int ATT_SMEM  = 21760 * 4;          // 87040
    static bool init = false;
    if (!init) {
        cudaFuncSetAttribute(gemm_mma<true>,  cudaFuncAttributeMaxDynamicSharedMemorySize, QKV_SMEM);
        cudaFuncSetAttribute(gemm_mma<false>, cudaFuncAttributeMaxDynamicSharedMemorySize, PROJ_SMEM);
        cudaFuncSetAttribute(attn_mma,        cudaFuncAttributeMaxDynamicSharedMemorySize, ATT_SMEM);
        init = true;
    }
    rms_kernel<<<32, 256>>>(x);
    gemm_mma<true><<<dim3(32, 12, 2), 256, QKV_SMEM>>>(qkv_w, x, nw, qkv_b, nullptr, nullptr);
    attn_mma<<<dim3(32, 16), 256, ATT_SMEM>>>();
    gemm_mma<false><<<dim3(32, 4, 2), 256, PROJ_SMEM>>>(proj_w, nullptr, nullptr, proj_b, x, out);
}

// round 5
// speedup vs baseline: 1.9977x; 1.0022x over previous
#include <cuda_runtime.h>
#include <math.h>

#define T   4096
#define CHN 512
#define M3  1536

__device__ float g_qkv[(size_t)2 * M3 * T];
__device__ float g_a[(size_t)2 * CHN * T];
__device__ float g_ir[(size_t)2 * T];

__device__ __forceinline__ unsigned tf32r(float x) {
    unsigned r; asm("cvt.rna.tf32.f32 %0, %1;" : "=r"(r) : "f"(x)); return r;
}
__device__ __forceinline__ void mma8(float c[4], const unsigned a[4],
                                     unsigned b0, unsigned b1) {
    asm volatile("mma.sync.aligned.m16n8k8.row.col.f32.tf32.tf32.f32 "
                 "{%0,%1,%2,%3}, {%4,%5,%6,%7}, {%8,%9}, {%0,%1,%2,%3};"
                 : "+f"(c[0]), "+f"(c[1]), "+f"(c[2]), "+f"(c[3])
                 : "r"(a[0]), "r"(a[1]), "r"(a[2]), "r"(a[3]), "r"(b0), "r"(b1));
}

__global__ void rms_kernel(const float* __restrict__ x) {
    int i = blockIdx.x * blockDim.x + threadIdx.x;
    int b = i >> 12, t = i & (T - 1);
    const float* xp = x + (size_t)b * CHN * T + t;
    float s = 0.f;
#pragma unroll 8
    for (int c = 0; c < CHN; c++) { float v = xp[(size_t)c * T]; s = fmaf(v, v, s); }
    g_ir[i] = 22.62741699796952f * rsqrtf(s * (1.0f / CHN) + 1e-8f);
}

// 128x128 tile, BK=32, 8 warps (warp 32x64). QKV: split tf32. proj: single.
template<bool QKV>
__global__ void __launch_bounds__(256) gemm_mma(
        const float* __restrict__ W, const float* __restrict__ Xin,
        const float* __restrict__ nw, const float* __restrict__ bias,
        const float* __restrict__ resid, float* __restrict__ outp)
{
    extern __shared__ unsigned smg[];
    const int RS = 36;
    unsigned* Ahi = smg;
    unsigned* Alo = QKV ? (Ahi + 128 * RS) : Ahi;
    unsigned* Bhi = Alo + 128 * RS;
    unsigned* Blo = QKV ? (Bhi + 128 * RS) : Bhi;

    int b = blockIdx.z, m0 = blockIdx.y * 128, t0 = blockIdx.x * 128;
    int tid = threadIdx.x, lane = tid & 31, wid = tid >> 5;
    int wm = wid >> 1, wn = wid & 1, g = lane >> 2, q = lane & 3;
    const float* Xb = (QKV ? Xin : (const float*)g_a) + (size_t)b * CHN * T;
    int bc4 = tid & 7, bt4 = tid >> 3;
    float4 ir4 = make_float4(1.f, 1.f, 1.f, 1.f);
    if (QKV) ir4 = *(const float4*)&g_ir[b * T + t0 + 4 * bt4];

    float acc[2][8][4];
#pragma unroll
    for (int mt = 0; mt < 2; mt++)
#pragma unroll
        for (int nt = 0; nt < 8; nt++)
#pragma unroll
            for (int i = 0; i < 4; i++) acc[mt][nt][i] = 0.f;

    for (int k0 = 0; k0 < CHN; k0 += 32) {
#pragma unroll
        for (int i = 0; i < 4; i++) {
            int idx = tid + i * 256, row = idx >> 3, c4 = idx & 7;
            float4 w = *(const float4*)&W[(size_t)(m0 + row) * CHN + k0 + 4 * c4];
            unsigned h0 = tf32r(w.x), h1 = tf32r(w.y), h2 = tf32r(w.z), h3 = tf32r(w.w);
            *(uint4*)&Ahi[row * RS + 4 * c4] = make_uint4(h0, h1, h2, h3);
            if (QKV)
                *(uint4*)&Alo[row * RS + 4 * c4] = make_uint4(
                    tf32r(w.x - __uint_as_float(h0)), tf32r(w.y - __uint_as_float(h1)),
                    tf32r(w.z - __uint_as_float(h2)), tf32r(w.w - __uint_as_float(h3)));
        }
        {
            float4 r[4];
#pragma unroll
            for (int j = 0; j < 4; j++) {
                r[j] = *(const float4*)&Xb[(size_t)(k0 + 4 * bc4 + j) * T + t0 + 4 * bt4];
                if (QKV) {
                    float s = nw[k0 + 4 * bc4 + j];
                    r[j].x *= s * ir4.x; r[j].y *= s * ir4.y;
                    r[j].z *= s * ir4.z; r[j].w *= s * ir4.w;
                }
            }
#pragma unroll
            for (int jp = 0; jp < 4; jp++) {
                float v0 = (&r[0].x)[jp], v1 = (&r[1].x)[jp];
                float v2 = (&r[2].x)[jp], v3 = (&r[3].x)[jp];
                unsigned h0 = tf32r(v0), h1 = tf32r(v1), h2 = tf32r(v2), h3 = tf32r(v3);
                *(uint4*)&Bhi[(4 * bt4 + jp) * RS + 4 * bc4] = make_uint4(h0, h1, h2, h3);
                if (QKV)
                    *(uint4*)&Blo[(4 * bt4 + jp) * RS + 4 * bc4] = make_uint4(
                        tf32r(v0 - __uint_as_float(h0)), tf32r(v1 - __uint_as_float(h1)),
                        tf32r(v2 - __uint_as_float(h2)), tf32r(v3 - __uint_as_float(h3)));
            }
        }
        __syncthreads();
#pragma unroll
        for (int ks = 0; ks < 4; ks++) {
            unsigned ah[2][4], al[2][4];
#pragma unroll
            for (int mt = 0; mt < 2; mt++) {
                int rb = wm * 32 + mt * 16;
                ah[mt][0] = Ahi[(rb + g) * RS + ks * 8 + q];
                ah[mt][1] = Ahi[(rb + g + 8) * RS + ks * 8 + q];
                ah[mt][2] = Ahi[(rb + g) * RS + ks * 8 + q + 4];
                ah[mt][3] = Ahi[(rb + g + 8) * RS + ks * 8 + q + 4];
                if (QKV) {
                    al[mt][0] = Alo[(rb + g) * RS + ks * 8 + q];
                    al[mt][1] = Alo[(rb + g + 8) * RS + ks * 8 + q];
                    al[mt][2] = Alo[(rb + g) * RS + ks * 8 + q + 4];
                    al[mt][3] = Alo[(rb + g + 8) * RS + ks * 8 + q + 4];
                }
            }
#pragma unroll
            for (int nt = 0; nt < 8; nt++) {
                int cb = wn * 64 + nt * 8;
                unsigned bh0 = Bhi[(cb + g) * RS + ks * 8 + q];
                unsigned bh1 = Bhi[(cb + g) * RS + ks * 8 + q + 4];
#pragma unroll
                for (int mt = 0; mt < 2; mt++) mma8(acc[mt][nt], ah[mt], bh0, bh1);
                if (QKV) {
                    unsigned bl0 = Blo[(cb + g) * RS + ks * 8 + q];
                    unsigned bl1 = Blo[(cb + g) * RS + ks * 8 + q + 4];
#pragma unroll
                    for (int mt = 0; mt < 2; mt++) {
                        mma8(acc[mt][nt], ah[mt], bl0, bl1);
                        mma8(acc[mt][nt], al[mt], bh0, bh1);
                    }
                }
            }
        }
        __syncthreads();
    }
#pragma unroll
    for (int mt = 0; mt < 2; mt++) {
        int row = m0 + wm * 32 + mt * 16 + g;
        float bi0 = bias[row], bi1 = bias[row + 8];
#pragma unroll
        for (int nt = 0; nt < 8; nt++) {
            int col = t0 + wn * 64 + nt * 8 + 2 * q;
            if (QKV) {
                *(float2*)&g_qkv[((size_t)b * M3 + row) * T + col] =
                    make_float2(acc[mt][nt][0] + bi0, acc[mt][nt][1] + bi0);
                *(float2*)&g_qkv[((size_t)b * M3 + row + 8) * T + col] =
                    make_float2(acc[mt][nt][2] + bi1, acc[mt][nt][3] + bi1);
            } else {
                size_t i0 = ((size_t)b * CHN + row) * T + col;
                size_t i1 = ((size_t)b * CHN + row + 8) * T + col;
                float2 r0 = *(const float2*)&resid[i0];
                float2 r1 = *(const float2*)&resid[i1];
                *(float2*)&outp[i0] = make_float2(acc[mt][nt][0] + bi0 + r0.x,
                                                  acc[mt][nt][1] + bi0 + r0.y);
                *(float2*)&outp[i1] = make_float2(acc[mt][nt][2] + bi1 + r1.x,
                                                  acc[mt][nt][3] + bi1 + r1.y);
            }
        }
    }
}

// Flash attention: block = 128 queries x 1 head, 8 warps x 16 rows.
// QK^T split tf32, PV single tf32. Ps overlays Qhi after frag load.
__global__ void __launch_bounds__(256) attn_mma() {
    extern __shared__ unsigned sma[];
    unsigned* Ps  = sma;              // [128][68] (= Qhi in prologue)
    unsigned* Qlo = sma + 8704;       // prologue only
    unsigned* Khi = sma + 8704;       // [64][68]
    unsigned* Klo = sma + 13056;      // [64][68]
    unsigned* Vs  = sma + 17408;      // [64][68]

    int t0 = blockIdx.x * 128, head = blockIdx.y;
    int b = head >> 3, hh = head & 7;
    const float* qb = g_qkv + ((size_t)b * M3 + hh * 192) * T;
    const float* kb = qb + (size_t)64 * T;
    const float* vb = qb + (size_t)128 * T;
    int tid = threadIdx.x, lane = tid & 31, wid = tid >> 5;
    int g = lane >> 2, q = lane & 3, rb = wid * 16;

    {   // Q fill: [c][t] -> [t][c] * 0.125, split
        int c4 = tid & 15;
#pragma unroll
        for (int it = 0; it < 2; it++) {
            int t4 = (tid >> 4) + it * 16;
            float4 r[4];
#pragma unroll
            for (int j = 0; j < 4; j++) {
                r[j] = *(const float4*)&qb[(size_t)(4 * c4 + j) * T + t0 + 4 * t4];
                r[j].x *= 0.125f; r[j].y *= 0.125f; r[j].z *= 0.125f; r[j].w *= 0.125f;
            }
#pragma unroll
            for (int jp = 0; jp < 4; jp++) {
                float v0 = (&r[0].x)[jp], v1 = (&r[1].x)[jp];
                float v2 = (&r[2].x)[jp], v3 = (&r[3].x)[jp];
                unsigned h0 = tf32r(v0), h1 = tf32r(v1), h2 = tf32r(v2), h3 = tf32r(v3);
                *(uint4*)&Ps[(4 * t4 + jp) * 68 + 4 * c4] = make_uint4(h0, h1, h2, h3);
                *(uint4*)&Qlo[(4 * t4 + jp) * 68 + 4 * c4] = make_uint4(
                    tf32r(v0 - __uint_as_float(h0)), tf32r(v1 - __uint_as_float(h1)),
                    tf32r(v2 - __uint_as_float(h2)), tf32r(v3 - __uint_as_float(h3)));
            }
        }
    }
    __syncthreads();
    unsigned qh[8][4], ql[8][4];
#pragma unroll
    for (int ks = 0; ks < 8; ks++) {
        qh[ks][0] = Ps[(rb + g) * 68 + ks * 8 + q];
        qh[ks][1] = Ps[(rb + g + 8) * 68 + ks * 8 + q];
        qh[ks][2] = Ps[(rb + g) * 68 + ks * 8 + q + 4];
        qh[ks][3] = Ps[(rb + g + 8) * 68 + ks * 8 + q + 4];
        ql[ks][0] = Qlo[(rb + g) * 68 + ks * 8 + q];
        ql[ks][1] = Qlo[(rb + g + 8) * 68 + ks * 8 + q];
        ql[ks][2] = Qlo[(rb + g) * 68 + ks * 8 + q + 4];
        ql[ks][3] = Qlo[(rb + g + 8) * 68 + ks * 8 + q + 4];
    }

    float o[8][4];
#pragma unroll
    for (int nt = 0; nt < 8; nt++)
#pragma unroll
        for (int i = 0; i < 4; i++) o[nt][i] = 0.f;
    float m_a = -1e30f, m_b = -1e30f, l_a = 0.f, l_b = 0.f;

    for (int s0 = 0; s0 < T; s0 += 64) {
        __syncthreads();
        {   // K fill (split) + V fill (single)
            int c4 = tid & 15, s4 = tid >> 4;
            float4 r[4];
#pragma unroll
            for (int j = 0; j < 4; j++)
                r[j] = *(const float4*)&kb[(size_t)(4 * c4 + j) * T + s0 + 4 * s4];
#pragma unroll
            for (int jp = 0; jp < 4; jp++) {
                float v0 = (&r[0].x)[jp], v1 = (&r[1].x)[jp];
                float v2 = (&r[2].x)[jp], v3 = (&r[3].x)[jp];
                unsigned h0 = tf32r(v0), h1 = tf32r(v1), h2 = tf32r(v2), h3 = tf32r(v3);
                *(uint4*)&Khi[(4 * s4 + jp) * 68 + 4 * c4] = make_uint4(h0, h1, h2, h3);
                *(uint4*)&Klo[(4 * s4 + jp) * 68 + 4 * c4] = make_uint4(
                    tf32r(v0 - __uint_as_float(h0)), tf32r(v1 - __uint_as_float(h1)),
                    tf32r(v2 - __uint_as_float(h2)), tf32r(v3 - __uint_as_float(h3)));
            }
#pragma unroll
            for (int i = 0; i < 4; i++) {
                int idx = tid + i * 256, c = idx >> 4, sv = idx & 15;
                float4 v = *(const float4*)&vb[(size_t)c * T + s0 + 4 * sv];
                *(uint4*)&Vs[c * 68 + 4 * sv] =
                    make_uint4(tf32r(v.x), tf32r(v.y), tf32r(v.z), tf32r(v.w));
            }
        }
        __syncthreads();

        float sacc[8][4];
#pragma unroll
        for (int nt = 0; nt < 8; nt++)
#pragma unroll
            for (int i = 0; i < 4; i++) sacc[nt][i] = 0.f;
#pragma unroll
        for (int ks = 0; ks < 8; ks++)
#pragma unroll
            for (int nt = 0; nt < 8; nt++) {
                unsigned bh0 = Khi[(nt * 8 + g) * 68 + ks * 8 + q];
                unsigned bh1 = Khi[(nt * 8 + g) * 68 + ks * 8 + q + 4];
                unsigned bl0 = Klo[(nt * 8 + g) * 68 + ks * 8 + q];
                unsigned bl1 = Klo[(nt * 8 + g) * 68 + ks * 8 + q + 4];
                mma8(sacc[nt], qh[ks], bh0, bh1);
                mma8(sacc[nt], qh[ks], bl0, bl1);
                mma8(sacc[nt], ql[ks], bh0, bh1);
            }

        float mx_a = -1e30f, mx_b = -1e30f;
#pragma unroll
        for (int nt = 0; nt < 8; nt++) {
            mx_a = fmaxf(mx_a, fmaxf(sacc[nt][0], sacc[nt][1]));
            mx_b = fmaxf(mx_b, fmaxf(sacc[nt][2], sacc[nt][3]));
        }
        mx_a = fmaxf(mx_a, __shfl_xor_sync(~0u, mx_a, 1));
        mx_a = fmaxf(mx_a, __shfl_xor_sync(~0u, mx_a, 2));
        mx_b = fmaxf(mx_b, __shfl_xor_sync(~0u, mx_b, 1));
        mx_b = fmaxf(mx_b, __shfl_xor_sync(~0u, mx_b, 2));
        float mn_a = fmaxf(m_a, mx_a), mn_b = fmaxf(m_b, mx_b);
        float ca = __expf(m_a - mn_a), cb = __expf(m_b - mn_b);
        float sum_a = 0.f, sum_b = 0.f;
#pragma unroll
        for (int nt = 0; nt < 8; nt++) {
            float p0 = __expf(sacc[nt][0] - mn_a), p1 = __expf(sacc[nt][1] - mn_a);
            float p2 = __expf(sacc[nt][2] - mn_b), p3 = __expf(sacc[nt][3] - mn_b);
            sum_a += p0 + p1; sum_b += p2 + p3;
            *(uint2*)&Ps[(rb + g) * 68 + nt * 8 + 2 * q] = make_uint2(tf32r(p0), tf32r(p1));
            *(uint2*)&Ps[(rb + g + 8) * 68 + nt * 8 + 2 * q] = make_uint2(tf32r(p2), tf32r(p3));
        }
        sum_a += __shfl_xor_sync(~0u, sum_a, 1);
        sum_a += __shfl_xor_sync(~0u, sum_a, 2);
        sum_b += __shfl_xor_sync(~0u, sum_b, 1);
        sum_b += __shfl_xor_sync(~0u, sum_b, 2);
        m_a = mn_a; m_b = mn_b;
        l_a = l_a * ca + sum_a; l_b = l_b * cb + sum_b;
#pragma unroll
        for (int nt = 0; nt < 8; nt++) {
            o[nt][0] *= ca; o[nt][1] *= ca; o[nt][2] *= cb; o[nt][3] *= cb;
        }
        __syncwarp();
#pragma unroll
        for (int ks = 0; ks < 8; ks++) {
            unsigned ph[4];
            ph[0] = Ps[(rb + g) * 68 + ks * 8 + q];
            ph[1] = Ps[(rb + g + 8) * 68 + ks * 8 + q];
            ph[2] = Ps[(rb + g) * 68 + ks * 8 + q + 4];
            ph[3] = Ps[(rb + g + 8) * 68 + ks * 8 + q + 4];
#pragma unroll
            for (int nt = 0; nt < 8; nt++) {
                unsigned bv0 = Vs[(nt * 8 + g) * 68 + ks * 8 + q];
                unsigned bv1 = Vs[(nt * 8 + g) * 68 + ks * 8 + q + 4];
                mma8(o[nt], ph, bv0, bv1);
            }
        }
    }

    float inv_a = 1.f / l_a, inv_b = 1.f / l_b;
    float* ab = g_a + ((size_t)b * CHN + hh * 64) * T;
#pragma unroll
    for (int nt = 0; nt < 8; nt++) {
        int c0 = nt * 8 + 2 * q;
        ab[(size_t)c0 * T + t0 + rb + g]           = o[nt][0] * inv_a;
        ab[(size_t)(c0 + 1) * T + t0 + rb + g]     = o[nt][1] * inv_a;
        ab[(size_t)c0 * T + t0 + rb + g + 8]       = o[nt][2] * inv_b;
        ab[(size_t)(c0 + 1) * T + t0 + rb + g + 8] = o[nt][3] * inv_b;
    }
}

extern "C" void kernel_launch(void* const* d_in, const int* in_sizes, int n_in,
                              void* d_out, int out_size) {
    const float* x      = (const float*)d_in[0];
    const float* nw     = (const float*)d_in[1];
    const float* qkv_w  = (const float*)d_in[2];
    const float* qkv_b  = (const float*)d_in[3];
    const float* proj_w = (const float*)d_in[4];
    const float* proj_b = (const float*)d_in[5];
    float* out = (float*)d_out;

    const int QKV_SMEM  = 4 * 128 * 36 * 4;   // 73728
    const int PROJ_SMEM = 2 * 128 * 36 * 4;   // 36864
    const int ATT_SMEM  = 21760 * 4;          // 87040
    static bool init = false;
    if (!init) {
        cudaFuncSetAttribute(gemm_mma<true>,  cudaFuncAttributeMaxDynamicSharedMemorySize, QKV_SMEM);
        cudaFuncSetAttribute(gemm_mma<false>, cudaFuncAttributeMaxDynamicSharedMemorySize, PROJ_SMEM);
        cudaFuncSetAttribute(attn_mma,        cudaFuncAttributeMaxDynamicSharedMemorySize, ATT_SMEM);
        init = true;
    }
    rms_kernel<<<32, 256>>>(x);
    gemm_mma<true><<<dim3(32, 12, 2), 256, QKV_SMEM>>>(qkv_w, x, nw, qkv_b, nullptr, nullptr);
    attn_mma<<<dim3(32, 16), 256, ATT_SMEM>>>();
    gemm_mma<false><<<dim3(32, 4, 2), 256, PROJ_SMEM>>>(proj_w, nullptr, nullptr, proj_b, x, out);
}

// round 6
// speedup vs baseline: 2.1931x; 1.0978x over previous
#include <cuda_runtime.h>
#include <cuda_bf16.h>
#include <math.h>

#define T   4096
#define CHN 512
#define M3  1536

__device__ float g_qkv[(size_t)2 * M3 * T];
__device__ float g_a[(size_t)2 * CHN * T];
__device__ float g_ir[(size_t)2 * T];

__device__ __forceinline__ unsigned tf32r(float x) {
    unsigned r; asm("cvt.rna.tf32.f32 %0, %1;" : "=r"(r) : "f"(x)); return r;
}
__device__ __forceinline__ void mma8(float c[4], const unsigned a[4],
                                     unsigned b0, unsigned b1) {
    asm volatile("mma.sync.aligned.m16n8k8.row.col.f32.tf32.tf32.f32 "
                 "{%0,%1,%2,%3}, {%4,%5,%6,%7}, {%8,%9}, {%0,%1,%2,%3};"
                 : "+f"(c[0]), "+f"(c[1]), "+f"(c[2]), "+f"(c[3])
                 : "r"(a[0]), "r"(a[1]), "r"(a[2]), "r"(a[3]), "r"(b0), "r"(b1));
}
// packed bf16 pair -> f32 bits of element with parity `odd` (bf16<<16 is exact f32)
__device__ __forceinline__ unsigned sel16(unsigned w, unsigned odd) {
    return odd ? (w & 0xffff0000u) : (w << 16);
}
__device__ __forceinline__ unsigned pack2bf(float a, float b) {
    __nv_bfloat162 p = __floats2bfloat162_rn(a, b);
    return *reinterpret_cast<unsigned*>(&p);
}

// ---------------------------------------------------------------------------
__global__ void __launch_bounds__(256) rms_kernel(const float* __restrict__ x) {
    __shared__ float red[8][32];
    int l = threadIdx.x & 31, w = threadIdx.x >> 5;
    int i = blockIdx.x * 32 + l;
    int b = i >> 12, t = i & (T - 1);
    const float* xp = x + (size_t)b * CHN * T + t + (size_t)(w * 64) * T;
    float s = 0.f;
#pragma unroll 16
    for (int j = 0; j < 64; j++) { float v = xp[(size_t)j * T]; s = fmaf(v, v, s); }
    red[w][l] = s;
    __syncthreads();
    if (w == 0) {
        float tot = red[0][l];
#pragma unroll
        for (int k = 1; k < 8; k++) tot += red[k][l];
        g_ir[i] = 22.62741699796952f * rsqrtf(tot * (1.f / CHN) + 1e-8f);
    }
}

// ---------------------------------------------------------------------------
// 128x128 tile, BK=32, 8 warps (warp 32x64). QKV: split (lo in bf16). proj: single.
template<bool QKV>
__global__ void __launch_bounds__(256, 2) gemm_mma(
        const float* __restrict__ W, const float* __restrict__ Xin,
        const float* __restrict__ nw, const float* __restrict__ bias,
        const float* __restrict__ resid, float* __restrict__ outp)
{
    extern __shared__ unsigned smg[];
    unsigned* Ahi = smg;              // [128][36]
    unsigned* Bhi = smg + 4608;       // [128][36]
    unsigned* Alo = smg + 9216;       // [128][20] packed bf16 (QKV only)
    unsigned* Blo = smg + 11776;      // [128][20]

    int b = blockIdx.z, m0 = blockIdx.y * 128, t0 = blockIdx.x * 128;
    int tid = threadIdx.x, lane = tid & 31, wid = tid >> 5;
    int wm = wid >> 1, wn = wid & 1, g = lane >> 2, q = lane & 3;
    unsigned odd = q & 1;
    const float* Xb = (QKV ? Xin : (const float*)g_a) + (size_t)b * CHN * T;
    int bc4 = tid & 7, bt4 = tid >> 3;
    float4 ir4 = make_float4(1.f, 1.f, 1.f, 1.f);
    if (QKV) ir4 = *(const float4*)&g_ir[b * T + t0 + 4 * bt4];

    float acc[2][8][4];
#pragma unroll
    for (int mt = 0; mt < 2; mt++)
#pragma unroll
        for (int nt = 0; nt < 8; nt++)
#pragma unroll
            for (int i = 0; i < 4; i++) acc[mt][nt][i] = 0.f;

    for (int k0 = 0; k0 < CHN; k0 += 32) {
#pragma unroll
        for (int i = 0; i < 4; i++) {
            int idx = tid + i * 256, row = idx >> 3, c4 = idx & 7;
            float4 w = *(const float4*)&W[(size_t)(m0 + row) * CHN + k0 + 4 * c4];
            unsigned h0 = tf32r(w.x), h1 = tf32r(w.y), h2 = tf32r(w.z), h3 = tf32r(w.w);
            *(uint4*)&Ahi[row * 36 + 4 * c4] = make_uint4(h0, h1, h2, h3);
            if (QKV)
                *(uint2*)&Alo[row * 20 + 2 * c4] = make_uint2(
                    pack2bf(w.x - __uint_as_float(h0), w.y - __uint_as_float(h1)),
                    pack2bf(w.z - __uint_as_float(h2), w.w - __uint_as_float(h3)));
        }
        {
            float4 r[4];
#pragma unroll
            for (int j = 0; j < 4; j++) {
                r[j] = *(const float4*)&Xb[(size_t)(k0 + 4 * bc4 + j) * T + t0 + 4 * bt4];
                if (QKV) {
                    float s = nw[k0 + 4 * bc4 + j];
                    r[j].x *= s * ir4.x; r[j].y *= s * ir4.y;
                    r[j].z *= s * ir4.z; r[j].w *= s * ir4.w;
                }
            }
#pragma unroll
            for (int jp = 0; jp < 4; jp++) {
                float v0 = (&r[0].x)[jp], v1 = (&r[1].x)[jp];
                float v2 = (&r[2].x)[jp], v3 = (&r[3].x)[jp];
                unsigned h0 = tf32r(v0), h1 = tf32r(v1), h2 = tf32r(v2), h3 = tf32r(v3);
                *(uint4*)&Bhi[(4 * bt4 + jp) * 36 + 4 * bc4] = make_uint4(h0, h1, h2, h3);
                if (QKV)
                    *(uint2*)&Blo[(4 * bt4 + jp) * 20 + 2 * bc4] = make_uint2(
                        pack2bf(v0 - __uint_as_float(h0), v1 - __uint_as_float(h1)),
                        pack2bf(v2 - __uint_as_float(h2), v3 - __uint_as_float(h3)));
            }
        }
        __syncthreads();
#pragma unroll
        for (int ks = 0; ks < 4; ks++) {
            unsigned ah[2][4], al[2][4];
#pragma unroll
            for (int mt = 0; mt < 2; mt++) {
                int rb = wm * 32 + mt * 16;
                ah[mt][0] = Ahi[(rb + g) * 36 + ks * 8 + q];
                ah[mt][1] = Ahi[(rb + g + 8) * 36 + ks * 8 + q];
                ah[mt][2] = Ahi[(rb + g) * 36 + ks * 8 + q + 4];
                ah[mt][3] = Ahi[(rb + g + 8) * 36 + ks * 8 + q + 4];
                if (QKV) {
                    int wq = ks * 4 + (q >> 1);
                    al[mt][0] = sel16(Alo[(rb + g) * 20 + wq], odd);
                    al[mt][1] = sel16(Alo[(rb + g + 8) * 20 + wq], odd);
                    al[mt][2] = sel16(Alo[(rb + g) * 20 + wq + 2], odd);
                    al[mt][3] = sel16(Alo[(rb + g + 8) * 20 + wq + 2], odd);
                }
            }
#pragma unroll
            for (int nt = 0; nt < 8; nt++) {
                int cb = wn * 64 + nt * 8;
                unsigned bh0 = Bhi[(cb + g) * 36 + ks * 8 + q];
                unsigned bh1 = Bhi[(cb + g) * 36 + ks * 8 + q + 4];
#pragma unroll
                for (int mt = 0; mt < 2; mt++) mma8(acc[mt][nt], ah[mt], bh0, bh1);
                if (QKV) {
                    int wq = ks * 4 + (q >> 1);
                    unsigned bl0 = sel16(Blo[(cb + g) * 20 + wq], odd);
                    unsigned bl1 = sel16(Blo[(cb + g) * 20 + wq + 2], odd);
#pragma unroll
                    for (int mt = 0; mt < 2; mt++) {
                        mma8(acc[mt][nt], ah[mt], bl0, bl1);
                        mma8(acc[mt][nt], al[mt], bh0, bh1);
                    }
                }
            }
        }
        __syncthreads();
    }
#pragma unroll
    for (int mt = 0; mt < 2; mt++) {
        int row = m0 + wm * 32 + mt * 16 + g;
        float bi0 = bias[row], bi1 = bias[row + 8];
#pragma unroll
        for (int nt = 0; nt < 8; nt++) {
            int col = t0 + wn * 64 + nt * 8 + 2 * q;
            if (QKV) {
                *(float2*)&g_qkv[((size_t)b * M3 + row) * T + col] =
                    make_float2(acc[mt][nt][0] + bi0, acc[mt][nt][1] + bi0);
                *(float2*)&g_qkv[((size_t)b * M3 + row + 8) * T + col] =
                    make_float2(acc[mt][nt][2] + bi1, acc[mt][nt][3] + bi1);
            } else {
                size_t i0 = ((size_t)b * CHN + row) * T + col;
                size_t i1 = ((size_t)b * CHN + row + 8) * T + col;
                float2 r0 = *(const float2*)&resid[i0];
                float2 r1 = *(const float2*)&resid[i1];
                *(float2*)&outp[i0] = make_float2(acc[mt][nt][0] + bi0 + r0.x,
                                                  acc[mt][nt][1] + bi0 + r0.y);
                *(float2*)&outp[i1] = make_float2(acc[mt][nt][2] + bi1 + r1.x,
                                                  acc[mt][nt][3] + bi1 + r1.y);
            }
        }
    }
}

// ---------------------------------------------------------------------------
// Flash attention: block = 128 queries x 1 head, 8 warps x 16 rows.
// QK^T split (lo parts bf16 in smem), PV single tf32. Ps overlays Qhi.
__global__ void __launch_bounds__(256, 2) attn_mma() {
    extern __shared__ unsigned sma[];
    unsigned* Ps   = sma;             // [128][68] (Qhi in prologue, then P)
    unsigned* Qlo  = sma + 8704;      // [128][36] packed bf16, persistent
    unsigned* Khi  = sma + 13312;     // [64][68]
    unsigned* Klo  = sma + 17664;     // [64][36] packed bf16
    unsigned* Vs   = sma + 19968;     // [64][68]

    int t0 = blockIdx.x * 128, head = blockIdx.y;
    int b = head >> 3, hh = head & 7;
    const float* qb = g_qkv + ((size_t)b * M3 + hh * 192) * T;
    const float* kb = qb + (size_t)64 * T;
    const float* vb = qb + (size_t)128 * T;
    int tid = threadIdx.x, lane = tid & 31, wid = tid >> 5;
    int g = lane >> 2, q = lane & 3, rb = wid * 16;
    unsigned odd = q & 1;

    {   // Q fill: [c][t] -> [t][c] * 0.125, hi tf32 into Ps, lo bf16 into Qlo
        int c4 = tid & 15;
#pragma unroll
        for (int it = 0; it < 2; it++) {
            int t4 = (tid >> 4) + it * 16;
            float4 r[4];
#pragma unroll
            for (int j = 0; j < 4; j++) {
                r[j] = *(const float4*)&qb[(size_t)(4 * c4 + j) * T + t0 + 4 * t4];
                r[j].x *= 0.125f; r[j].y *= 0.125f; r[j].z *= 0.125f; r[j].w *= 0.125f;
            }
#pragma unroll
            for (int jp = 0; jp < 4; jp++) {
                float v0 = (&r[0].x)[jp], v1 = (&r[1].x)[jp];
                float v2 = (&r[2].x)[jp], v3 = (&r[3].x)[jp];
                unsigned h0 = tf32r(v0), h1 = tf32r(v1), h2 = tf32r(v2), h3 = tf32r(v3);
                *(uint4*)&Ps[(4 * t4 + jp) * 68 + 4 * c4] = make_uint4(h0, h1, h2, h3);
                *(uint2*)&Qlo[(4 * t4 + jp) * 36 + 2 * c4] = make_uint2(
                    pack2bf(v0 - __uint_as_float(h0), v1 - __uint_as_float(h1)),
                    pack2bf(v2 - __uint_as_float(h2), v3 - __uint_as_float(h3)));
            }
        }
    }
    __syncthreads();
    unsigned qh[8][4];
#pragma unroll
    for (int ks = 0; ks < 8; ks++) {
        qh[ks][0] = Ps[(rb + g) * 68 + ks * 8 + q];
        qh[ks][1] = Ps[(rb + g + 8) * 68 + ks * 8 + q];
        qh[ks][2] = Ps[(rb + g) * 68 + ks * 8 + q + 4];
        qh[ks][3] = Ps[(rb + g + 8) * 68 + ks * 8 + q + 4];
    }

    float o[8][4];
#pragma unroll
    for (int nt = 0; nt < 8; nt++)
#pragma unroll
        for (int i = 0; i < 4; i++) o[nt][i] = 0.f;
    float m_a = -1e30f, m_b = -1e30f, l_a = 0.f, l_b = 0.f;

    for (int s0 = 0; s0 < T; s0 += 64) {
        __syncthreads();
        {   // K fill (hi tf32 + lo bf16) and V fill (single tf32)
            int c4 = tid & 15, s4 = tid >> 4;
            float4 r[4];
#pragma unroll
            for (int j = 0; j < 4; j++)
                r[j] = *(const float4*)&kb[(size_t)(4 * c4 + j) * T + s0 + 4 * s4];
#pragma unroll
            for (int jp = 0; jp < 4; jp++) {
                float v0 = (&r[0].x)[jp], v1 = (&r[1].x)[jp];
                float v2 = (&r[2].x)[jp], v3 = (&r[3].x)[jp];
                unsigned h0 = tf32r(v0), h1 = tf32r(v1), h2 = tf32r(v2), h3 = tf32r(v3);
                *(uint4*)&Khi[(4 * s4 + jp) * 68 + 4 * c4] = make_uint4(h0, h1, h2, h3);
                *(uint2*)&Klo[(4 * s4 + jp) * 36 + 2 * c4] = make_uint2(
                    pack2bf(v0 - __uint_as_float(h0), v1 - __uint_as_float(h1)),
                    pack2bf(v2 - __uint_as_float(h2), v3 - __uint_as_float(h3)));
            }
#pragma unroll
            for (int i = 0; i < 4; i++) {
                int idx = tid + i * 256, c = idx >> 4, sv = idx & 15;
                float4 v = *(const float4*)&vb[(size_t)c * T + s0 + 4 * sv];
                *(uint4*)&Vs[c * 68 + 4 * sv] =
                    make_uint4(tf32r(v.x), tf32r(v.y), tf32r(v.z), tf32r(v.w));
            }
        }
        __syncthreads();

        float sacc[8][4];
#pragma unroll
        for (int nt = 0; nt < 8; nt++)
#pragma unroll
            for (int i = 0; i < 4; i++) sacc[nt][i] = 0.f;
#pragma unroll
        for (int ks = 0; ks < 8; ks++) {
            unsigned al[4];
            {
                int wq = ks * 4 + (q >> 1);
                al[0] = sel16(Qlo[(rb + g) * 36 + wq], odd);
                al[1] = sel16(Qlo[(rb + g + 8) * 36 + wq], odd);
                al[2] = sel16(Qlo[(rb + g) * 36 + wq + 2], odd);
                al[3] = sel16(Qlo[(rb + g + 8) * 36 + wq + 2], odd);
            }
#pragma unroll
            for (int nt = 0; nt < 8; nt++) {
                unsigned bh0 = Khi[(nt * 8 + g) * 68 + ks * 8 + q];
                unsigned bh1 = Khi[(nt * 8 + g) * 68 + ks * 8 + q + 4];
                int wq = ks * 4 + (q >> 1);
                unsigned bl0 = sel16(Klo[(nt * 8 + g) * 36 + wq], odd);
                unsigned bl1 = sel16(Klo[(nt * 8 + g) * 36 + wq + 2], odd);
                mma8(sacc[nt], qh[ks], bh0, bh1);
                mma8(sacc[nt], qh[ks], bl0, bl1);
                mma8(sacc[nt], al, bh0, bh1);
            }
        }

        float mx_a = -1e30f, mx_b = -1e30f;
#pragma unroll
        for (int nt = 0; nt < 8; nt++) {
            mx_a = fmaxf(mx_a, fmaxf(sacc[nt][0], sacc[nt][1]));
            mx_b = fmaxf(mx_b, fmaxf(sacc[nt][2], sacc[nt][3]));
        }
        mx_a = fmaxf(mx_a, __shfl_xor_sync(~0u, mx_a, 1));
        mx_a = fmaxf(mx_a, __shfl_xor_sync(~0u, mx_a, 2));
        mx_b = fmaxf(mx_b, __shfl_xor_sync(~0u, mx_b, 1));
        mx_b = fmaxf(mx_b, __shfl_xor_sync(~0u, mx_b, 2));
        float mn_a = fmaxf(m_a, mx_a), mn_b = fmaxf(m_b, mx_b);
        float ca = __expf(m_a - mn_a), cb = __expf(m_b - mn_b);
        float sum_a = 0.f, sum_b = 0.f;
#pragma unroll
        for (int nt = 0; nt < 8; nt++) {
            float p0 = __expf(sacc[nt][0] - mn_a), p1 = __expf(sacc[nt][1] - mn_a);
            float p2 = __expf(sacc[nt][2] - mn_b), p3 = __expf(sacc[nt][3] - mn_b);
            sum_a += p0 + p1; sum_b += p2 + p3;
            *(uint2*)&Ps[(rb + g) * 68 + nt * 8 + 2 * q] = make_uint2(tf32r(p0), tf32r(p1));
            *(uint2*)&Ps[(rb + g + 8) * 68 + nt * 8 + 2 * q] = make_uint2(tf32r(p2), tf32r(p3));
        }
        sum_a += __shfl_xor_sync(~0u, sum_a, 1);
        sum_a += __shfl_xor_sync(~0u, sum_a, 2);
        sum_b += __shfl_xor_sync(~0u, sum_b, 1);
        sum_b += __shfl_xor_sync(~0u, sum_b, 2);
        m_a = mn_a; m_b = mn_b;
        l_a = l_a * ca + sum_a; l_b = l_b * cb + sum_b;
#pragma unroll
        for (int nt = 0; nt < 8; nt++) {
            o[nt][0] *= ca; o[nt][1] *= ca; o[nt][2] *= cb; o[nt][3] *= cb;
        }
        __syncwarp();
#pragma unroll
        for (int ks = 0; ks < 8; ks++) {
            unsigned ph[4];
            ph[0] = Ps[(rb + g) * 68 + ks * 8 + q];
            ph[1] = Ps[(rb + g + 8) * 68 + ks * 8 + q];
            ph[2] = Ps[(rb + g) * 68 + ks * 8 + q + 4];
            ph[3] = Ps[(rb + g + 8) * 68 + ks * 8 + q + 4];
#pragma unroll
            for (int nt = 0; nt < 8; nt++) {
                unsigned bv0 = Vs[(nt * 8 + g) * 68 + ks * 8 + q];
                unsigned bv1 = Vs[(nt * 8 + g) * 68 + ks * 8 + q + 4];
                mma8(o[nt], ph, bv0, bv1);
            }
        }
    }

    float inv_a = 1.f / l_a, inv_b = 1.f / l_b;
    float* ab = g_a + ((size_t)b * CHN + hh * 64) * T;
#pragma unroll
    for (int nt = 0; nt < 8; nt++) {
        int c0 = nt * 8 + 2 * q;
        ab[(size_t)c0 * T + t0 + rb + g]           = o[nt][0] * inv_a;
        ab[(size_t)(c0 + 1) * T + t0 + rb + g]     = o[nt][1] * inv_a;
        ab[(size_t)c0 * T + t0 + rb + g + 8]       = o[nt][2] * inv_b;
        ab[(size_t)(c0 + 1) * T + t0 + rb + g + 8] = o[nt][3] * inv_b;
    }
}

// ---------------------------------------------------------------------------
extern "C" void kernel_launch(void* const* d_in, const int* in_sizes, int n_in,
                              void* d_out, int out_size) {
    const float* x      = (const float*)d_in[0];
    const float* nw     = (const float*)d_in[1];
    const float* qkv_w  = (const float*)d_in[2];
    const float* qkv_b  = (const float*)d_in[3];
    const float* proj_w = (const float*)d_in[4];
    const float* proj_b = (const float*)d_in[5];
    float* out = (float*)d_out;

    const int QKV_SMEM  = 14336 * 4;  // 57344
    const int PROJ_SMEM = 9216 * 4;   // 36864
    const int ATT_SMEM  = 24320 * 4;  // 97280
    static bool init = false;
    if (!init) {
        cudaFuncSetAttribute(gemm_mma<true>,  cudaFuncAttributeMaxDynamicSharedMemorySize, QKV_SMEM);
        cudaFuncSetAttribute(gemm_mma<false>, cudaFuncAttributeMaxDynamicSharedMemorySize, PROJ_SMEM);
        cudaFuncSetAttribute(attn_mma,        cudaFuncAttributeMaxDynamicSharedMemorySize, ATT_SMEM);
        cudaFuncSetAttribute(gemm_mma<true>,  cudaFuncAttributePreferredSharedMemoryCarveout, 100);
        cudaFuncSetAttribute(gemm_mma<false>, cudaFuncAttributePreferredSharedMemoryCarveout, 100);
        cudaFuncSetAttribute(attn_mma,        cudaFuncAttributePreferredSharedMemoryCarveout, 100);
        init = true;
    }
    rms_kernel<<<256, 256>>>(x);
    gemm_mma<true><<<dim3(32, 12, 2), 256, QKV_SMEM>>>(qkv_w, x, nw, qkv_b, nullptr, nullptr);
    attn_mma<<<dim3(32, 16), 256, ATT_SMEM>>>();
    gemm_mma<false><<<dim3(32, 4, 2), 256, PROJ_SMEM>>>(proj_w, nullptr, nullptr, proj_b, x, out);
}

// round 7
// speedup vs baseline: 2.3112x; 1.0538x over previous
#include <cuda_runtime.h>
#include <cuda_bf16.h>
#include <math.h>

#define T   4096
#define CHN 512
#define M3  1536

__device__ float g_qkv[(size_t)2 * M3 * T];
__device__ float g_a[(size_t)2 * CHN * T];
__device__ float g_ir[(size_t)2 * T];

__device__ __forceinline__ unsigned tf32r(float x) {
    unsigned r; asm("cvt.rna.tf32.f32 %0, %1;" : "=r"(r) : "f"(x)); return r;
}
__device__ __forceinline__ void mma8(float c[4], const unsigned a[4],
                                     unsigned b0, unsigned b1) {
    asm volatile("mma.sync.aligned.m16n8k8.row.col.f32.tf32.tf32.f32 "
                 "{%0,%1,%2,%3}, {%4,%5,%6,%7}, {%8,%9}, {%0,%1,%2,%3};"
                 : "+f"(c[0]), "+f"(c[1]), "+f"(c[2]), "+f"(c[3])
                 : "r"(a[0]), "r"(a[1]), "r"(a[2]), "r"(a[3]), "r"(b0), "r"(b1));
}
__device__ __forceinline__ void ldsm4(unsigned r[4], unsigned addr) {
    asm volatile("ldmatrix.sync.aligned.m8n8.x4.shared.b16 {%0,%1,%2,%3}, [%4];"
                 : "=r"(r[0]), "=r"(r[1]), "=r"(r[2]), "=r"(r[3]) : "r"(addr));
}
__device__ __forceinline__ unsigned sel16(unsigned w, unsigned odd) {
    return odd ? (w & 0xffff0000u) : (w << 16);
}
__device__ __forceinline__ unsigned pack2bf(float a, float b) {
    __nv_bfloat162 p = __floats2bfloat162_rn(a, b);
    return *reinterpret_cast<unsigned*>(&p);
}

// ---------------------------------------------------------------------------
__global__ void __launch_bounds__(256) rms_kernel(const float* __restrict__ x) {
    __shared__ float red[8][32];
    int l = threadIdx.x & 31, w = threadIdx.x >> 5;
    int i = blockIdx.x * 32 + l;
    int b = i >> 12, t = i & (T - 1);
    const float* xp = x + (size_t)b * CHN * T + t + (size_t)(w * 64) * T;
    float s = 0.f;
#pragma unroll 16
    for (int j = 0; j < 64; j++) { float v = xp[(size_t)j * T]; s = fmaf(v, v, s); }
    red[w][l] = s;
    __syncthreads();
    if (w == 0) {
        float tot = red[0][l];
#pragma unroll
        for (int k = 1; k < 8; k++) tot += red[k][l];
        g_ir[i] = 22.62741699796952f * rsqrtf(tot * (1.f / CHN) + 1e-8f);
    }
}

// ---------------------------------------------------------------------------
// 128x128 tile, BK=32, 8 warps (warp 32x64). QKV: split (lo bf16). proj: single.
template<bool QKV>
__global__ void __launch_bounds__(256, 2) gemm_mma(
        const float* __restrict__ W, const float* __restrict__ Xin,
        const float* __restrict__ nw, const float* __restrict__ bias,
        const float* __restrict__ resid, float* __restrict__ outp)
{
    extern __shared__ unsigned smg[];
    unsigned* Ahi = smg;              // [128][36]
    unsigned* Bhi = smg + 4608;       // [128][36]
    unsigned* Alo = smg + 9216;       // [128][20] packed bf16 (QKV only)
    unsigned* Blo = smg + 11776;      // [128][20]
    unsigned baseA = (unsigned)__cvta_generic_to_shared(Ahi);
    unsigned baseB = (unsigned)__cvta_generic_to_shared(Bhi);

    int b = blockIdx.z, m0 = blockIdx.y * 128, t0 = blockIdx.x * 128;
    int tid = threadIdx.x, lane = tid & 31, wid = tid >> 5;
    int wm = wid >> 1, wn = wid & 1, g = lane >> 2, q = lane & 3;
    int grp = lane >> 3, lam = lane & 7;
    unsigned odd = q & 1;
    const float* Xb = (QKV ? Xin : (const float*)g_a) + (size_t)b * CHN * T;
    int bc4 = tid & 7, bt4 = tid >> 3;
    float4 ir4 = make_float4(1.f, 1.f, 1.f, 1.f);
    if (QKV) ir4 = *(const float4*)&g_ir[b * T + t0 + 4 * bt4];

    float acc[2][8][4];
#pragma unroll
    for (int mt = 0; mt < 2; mt++)
#pragma unroll
        for (int nt = 0; nt < 8; nt++)
#pragma unroll
            for (int i = 0; i < 4; i++) acc[mt][nt][i] = 0.f;

    for (int k0 = 0; k0 < CHN; k0 += 32) {
#pragma unroll
        for (int i = 0; i < 4; i++) {
            int idx = tid + i * 256, row = idx >> 3, c4 = idx & 7;
            float4 w = *(const float4*)&W[(size_t)(m0 + row) * CHN + k0 + 4 * c4];
            unsigned h0 = tf32r(w.x), h1 = tf32r(w.y), h2 = tf32r(w.z), h3 = tf32r(w.w);
            *(uint4*)&Ahi[row * 36 + 4 * c4] = make_uint4(h0, h1, h2, h3);
            if (QKV)
                *(uint2*)&Alo[row * 20 + 2 * c4] = make_uint2(
                    pack2bf(w.x - __uint_as_float(h0), w.y - __uint_as_float(h1)),
                    pack2bf(w.z - __uint_as_float(h2), w.w - __uint_as_float(h3)));
        }
        {
            float4 r[4];
#pragma unroll
            for (int j = 0; j < 4; j++) {
                r[j] = *(const float4*)&Xb[(size_t)(k0 + 4 * bc4 + j) * T + t0 + 4 * bt4];
                if (QKV) {
                    float s = nw[k0 + 4 * bc4 + j];
                    r[j].x *= s * ir4.x; r[j].y *= s * ir4.y;
                    r[j].z *= s * ir4.z; r[j].w *= s * ir4.w;
                }
            }
#pragma unroll
            for (int jp = 0; jp < 4; jp++) {
                float v0 = (&r[0].x)[jp], v1 = (&r[1].x)[jp];
                float v2 = (&r[2].x)[jp], v3 = (&r[3].x)[jp];
                unsigned h0 = tf32r(v0), h1 = tf32r(v1), h2 = tf32r(v2), h3 = tf32r(v3);
                *(uint4*)&Bhi[(4 * bt4 + jp) * 36 + 4 * bc4] = make_uint4(h0, h1, h2, h3);
                if (QKV)
                    *(uint2*)&Blo[(4 * bt4 + jp) * 20 + 2 * bc4] = make_uint2(
                        pack2bf(v0 - __uint_as_float(h0), v1 - __uint_as_float(h1)),
                        pack2bf(v2 - __uint_as_float(h2), v3 - __uint_as_float(h3)));
            }
        }
        __syncthreads();
#pragma unroll
        for (int ks = 0; ks < 4; ks++) {
            unsigned ah[2][4], al[2][4];
#pragma unroll
            for (int mt = 0; mt < 2; mt++) {
                // A-frag: row += (grp&1)*8, col += (grp>>1)*4
                unsigned row = wm * 32 + mt * 16 + (grp & 1) * 8 + lam;
                unsigned col = ks * 8 + (grp >> 1) * 4;
                ldsm4(ah[mt], baseA + (row * 36 + col) * 4);
                if (QKV) {
                    int rb = wm * 32 + mt * 16, wq = ks * 4 + (q >> 1);
                    al[mt][0] = sel16(Alo[(rb + g) * 20 + wq], odd);
                    al[mt][1] = sel16(Alo[(rb + g + 8) * 20 + wq], odd);
                    al[mt][2] = sel16(Alo[(rb + g) * 20 + wq + 2], odd);
                    al[mt][3] = sel16(Alo[(rb + g + 8) * 20 + wq + 2], odd);
                }
            }
#pragma unroll
            for (int ntp = 0; ntp < 8; ntp += 2) {
                // B-frag: row += (grp>>1)*8, col += (grp&1)*4
                unsigned row = wn * 64 + (ntp + (grp >> 1)) * 8 + lam;
                unsigned col = ks * 8 + (grp & 1) * 4;
                unsigned bh[4];
                ldsm4(bh, baseB + (row * 36 + col) * 4);
#pragma unroll
                for (int mt = 0; mt < 2; mt++) {
                    mma8(acc[mt][ntp], ah[mt], bh[0], bh[1]);
                    mma8(acc[mt][ntp + 1], ah[mt], bh[2], bh[3]);
                }
                if (QKV) {
                    int wq = ks * 4 + (q >> 1);
#pragma unroll
                    for (int d = 0; d < 2; d++) {
                        int cb = wn * 64 + (ntp + d) * 8;
                        unsigned bl0 = sel16(Blo[(cb + g) * 20 + wq], odd);
                        unsigned bl1 = sel16(Blo[(cb + g) * 20 + wq + 2], odd);
#pragma unroll
                        for (int mt = 0; mt < 2; mt++) {
                            mma8(acc[mt][ntp + d], ah[mt], bl0, bl1);
                            mma8(acc[mt][ntp + d], al[mt], bh[2 * d], bh[2 * d + 1]);
                        }
                    }
                }
            }
        }
        __syncthreads();
    }
#pragma unroll
    for (int mt = 0; mt < 2; mt++) {
        int row = m0 + wm * 32 + mt * 16 + g;
        float bi0 = bias[row], bi1 = bias[row + 8];
#pragma unroll
        for (int nt = 0; nt < 8; nt++) {
            int col = t0 + wn * 64 + nt * 8 + 2 * q;
            if (QKV) {
                *(float2*)&g_qkv[((size_t)b * M3 + row) * T + col] =
                    make_float2(acc[mt][nt][0] + bi0, acc[mt][nt][1] + bi0);
                *(float2*)&g_qkv[((size_t)b * M3 + row + 8) * T + col] =
                    make_float2(acc[mt][nt][2] + bi1, acc[mt][nt][3] + bi1);
            } else {
                size_t i0 = ((size_t)b * CHN + row) * T + col;
                size_t i1 = ((size_t)b * CHN + row + 8) * T + col;
                float2 r0 = *(const float2*)&resid[i0];
                float2 r1 = *(const float2*)&resid[i1];
                *(float2*)&outp[i0] = make_float2(acc[mt][nt][0] + bi0 + r0.x,
                                                  acc[mt][nt][1] + bi0 + r0.y);
                *(float2*)&outp[i1] = make_float2(acc[mt][nt][2] + bi1 + r1.x,
                                                  acc[mt][nt][3] + bi1 + r1.y);
            }
        }
    }
}

// ---------------------------------------------------------------------------
// Flash attention: block = 128 queries x 1 head, 8 warps x 16 rows.
// QK^T split tf32 (Klo expanded tf32 for ldmatrix; Qlo packed bf16), PV single.
__global__ void __launch_bounds__(256, 2) attn_mma() {
    extern __shared__ unsigned sma[];
    unsigned* Ps   = sma;             // [128][68] (Qhi in prologue, then P)
    unsigned* Qlo  = sma + 8704;      // [128][36] packed bf16, persistent
    unsigned* Khi  = sma + 13312;     // [64][68]
    unsigned* Klo  = sma + 17664;     // [64][68] tf32
    unsigned* Vs   = sma + 22016;     // [64][68]
    unsigned basePs = (unsigned)__cvta_generic_to_shared(Ps);
    unsigned baseKh = (unsigned)__cvta_generic_to_shared(Khi);
    unsigned baseKl = (unsigned)__cvta_generic_to_shared(Klo);
    unsigned baseV  = (unsigned)__cvta_generic_to_shared(Vs);

    int t0 = blockIdx.x * 128, head = blockIdx.y;
    int b = head >> 3, hh = head & 7;
    const float* qb = g_qkv + ((size_t)b * M3 + hh * 192) * T;
    const float* kb = qb + (size_t)64 * T;
    const float* vb = qb + (size_t)128 * T;
    int tid = threadIdx.x, lane = tid & 31, wid = tid >> 5;
    int g = lane >> 2, q = lane & 3, rb = wid * 16;
    int grp = lane >> 3, lam = lane & 7;
    unsigned odd = q & 1;

    {   // Q fill: [c][t] -> [t][c] * 0.125, hi tf32 into Ps, lo bf16 into Qlo
        int c4 = tid & 15;
#pragma unroll
        for (int it = 0; it < 2; it++) {
            int t4 = (tid >> 4) + it * 16;
            float4 r[4];
#pragma unroll
            for (int j = 0; j < 4; j++) {
                r[j] = *(const float4*)&qb[(size_t)(4 * c4 + j) * T + t0 + 4 * t4];
                r[j].x *= 0.125f; r[j].y *= 0.125f; r[j].z *= 0.125f; r[j].w *= 0.125f;
            }
#pragma unroll
            for (int jp = 0; jp < 4; jp++) {
                float v0 = (&r[0].x)[jp], v1 = (&r[1].x)[jp];
                float v2 = (&r[2].x)[jp], v3 = (&r[3].x)[jp];
                unsigned h0 = tf32r(v0), h1 = tf32r(v1), h2 = tf32r(v2), h3 = tf32r(v3);
                *(uint4*)&Ps[(4 * t4 + jp) * 68 + 4 * c4] = make_uint4(h0, h1, h2, h3);
                *(uint2*)&Qlo[(4 * t4 + jp) * 36 + 2 * c4] = make_uint2(
                    pack2bf(v0 - __uint_as_float(h0), v1 - __uint_as_float(h1)),
                    pack2bf(v2 - __uint_as_float(h2), v3 - __uint_as_float(h3)));
            }
        }
    }
    __syncthreads();
    unsigned qh[8][4];
#pragma unroll
    for (int ks = 0; ks < 8; ks++) {
        unsigned row = rb + (grp & 1) * 8 + lam;
        unsigned col = ks * 8 + (grp >> 1) * 4;
        ldsm4(qh[ks], basePs + (row * 68 + col) * 4);
    }

    float o[8][4];
#pragma unroll
    for (int nt = 0; nt < 8; nt++)
#pragma unroll
        for (int i = 0; i < 4; i++) o[nt][i] = 0.f;
    float m_a = -1e30f, m_b = -1e30f, l_a = 0.f, l_b = 0.f;

    for (int s0 = 0; s0 < T; s0 += 64) {
        __syncthreads();
        {   // K fill (hi + lo tf32) and V fill (single tf32)
            int c4 = tid & 15, s4 = tid >> 4;
            float4 r[4];
#pragma unroll
            for (int j = 0; j < 4; j++)
                r[j] = *(const float4*)&kb[(size_t)(4 * c4 + j) * T + s0 + 4 * s4];
#pragma unroll
            for (int jp = 0; jp < 4; jp++) {
                float v0 = (&r[0].x)[jp], v1 = (&r[1].x)[jp];
                float v2 = (&r[2].x)[jp], v3 = (&r[3].x)[jp];
                unsigned h0 = tf32r(v0), h1 = tf32r(v1), h2 = tf32r(v2), h3 = tf32r(v3);
                *(uint4*)&Khi[(4 * s4 + jp) * 68 + 4 * c4] = make_uint4(h0, h1, h2, h3);
                *(uint4*)&Klo[(4 * s4 + jp) * 68 + 4 * c4] = make_uint4(
                    tf32r(v0 - __uint_as_float(h0)), tf32r(v1 - __uint_as_float(h1)),
                    tf32r(v2 - __uint_as_float(h2)), tf32r(v3 - __uint_as_float(h3)));
            }
#pragma unroll
            for (int i = 0; i < 4; i++) {
                int idx = tid + i * 256, c = idx >> 4, sv = idx & 15;
                float4 v = *(const float4*)&vb[(size_t)c * T + s0 + 4 * sv];
                *(uint4*)&Vs[c * 68 + 4 * sv] =
                    make_uint4(tf32r(v.x), tf32r(v.y), tf32r(v.z), tf32r(v.w));
            }
        }
        __syncthreads();

        float sacc[8][4];
#pragma unroll
        for (int nt = 0; nt < 8; nt++)
#pragma unroll
            for (int i = 0; i < 4; i++) sacc[nt][i] = 0.f;
#pragma unroll
        for (int ks = 0; ks < 8; ks++) {
            unsigned al[4];
            {
                int wq = ks * 4 + (q >> 1);
                al[0] = sel16(Qlo[(rb + g) * 36 + wq], odd);
                al[1] = sel16(Qlo[(rb + g + 8) * 36 + wq], odd);
                al[2] = sel16(Qlo[(rb + g) * 36 + wq + 2], odd);
                al[3] = sel16(Qlo[(rb + g + 8) * 36 + wq + 2], odd);
            }
#pragma unroll
            for (int ntp = 0; ntp < 8; ntp += 2) {
                unsigned row = (ntp + (grp >> 1)) * 8 + lam;
                unsigned col = ks * 8 + (grp & 1) * 4;
                unsigned off = (row * 68 + col) * 4;
                unsigned kh[4], kl[4];
                ldsm4(kh, baseKh + off);
                ldsm4(kl, baseKl + off);
                mma8(sacc[ntp], qh[ks], kh[0], kh[1]);
                mma8(sacc[ntp], qh[ks], kl[0], kl[1]);
                mma8(sacc[ntp], al, kh[0], kh[1]);
                mma8(sacc[ntp + 1], qh[ks], kh[2], kh[3]);
                mma8(sacc[ntp + 1], qh[ks], kl[2], kl[3]);
                mma8(sacc[ntp + 1], al, kh[2], kh[3]);
            }
        }

        float mx_a = -1e30f, mx_b = -1e30f;
#pragma unroll
        for (int nt = 0; nt < 8; nt++) {
            mx_a = fmaxf(mx_a, fmaxf(sacc[nt][0], sacc[nt][1]));
            mx_b = fmaxf(mx_b, fmaxf(sacc[nt][2], sacc[nt][3]));
        }
        mx_a = fmaxf(mx_a, __shfl_xor_sync(~0u, mx_a, 1));
        mx_a = fmaxf(mx_a, __shfl_xor_sync(~0u, mx_a, 2));
        mx_b = fmaxf(mx_b, __shfl_xor_sync(~0u, mx_b, 1));
        mx_b = fmaxf(mx_b, __shfl_xor_sync(~0u, mx_b, 2));
        float mn_a = fmaxf(m_a, mx_a), mn_b = fmaxf(m_b, mx_b);
        float ca = __expf(m_a - mn_a), cb = __expf(m_b - mn_b);
        float sum_a = 0.f, sum_b = 0.f;
#pragma unroll
        for (int nt = 0; nt < 8; nt++) {
            float p0 = __expf(sacc[nt][0] - mn_a), p1 = __expf(sacc[nt][1] - mn_a);
            float p2 = __expf(sacc[nt][2] - mn_b), p3 = __expf(sacc[nt][3] - mn_b);
            sum_a += p0 + p1; sum_b += p2 + p3;
            *(uint2*)&Ps[(rb + g) * 68 + nt * 8 + 2 * q] = make_uint2(tf32r(p0), tf32r(p1));
            *(uint2*)&Ps[(rb + g + 8) * 68 + nt * 8 + 2 * q] = make_uint2(tf32r(p2), tf32r(p3));
        }
        sum_a += __shfl_xor_sync(~0u, sum_a, 1);
        sum_a += __shfl_xor_sync(~0u, sum_a, 2);
        sum_b += __shfl_xor_sync(~0u, sum_b, 1);
        sum_b += __shfl_xor_sync(~0u, sum_b, 2);
        m_a = mn_a; m_b = mn_b;
        l_a = l_a * ca + sum_a; l_b = l_b * cb + sum_b;
#pragma unroll
        for (int nt = 0; nt < 8; nt++) {
            o[nt][0] *= ca; o[nt][1] *= ca; o[nt][2] *= cb; o[nt][3] *= cb;
        }
        __syncwarp();
#pragma unroll
        for (int ks = 0; ks < 8; ks++) {
            unsigned ph[4];
            {
                unsigned row = rb + (grp & 1) * 8 + lam;
                unsigned col = ks * 8 + (grp >> 1) * 4;
                ldsm4(ph, basePs + (row * 68 + col) * 4);
            }
#pragma unroll
            for (int ntp = 0; ntp < 8; ntp += 2) {
                unsigned row = (ntp + (grp >> 1)) * 8 + lam;
                unsigned col = ks * 8 + (grp & 1) * 4;
                unsigned vv[4];
                ldsm4(vv, baseV + (row * 68 + col) * 4);
                mma8(o[ntp], ph, vv[0], vv[1]);
                mma8(o[ntp + 1], ph, vv[2], vv[3]);
            }
        }
    }

    float inv_a = 1.f / l_a, inv_b = 1.f / l_b;
    float* ab = g_a + ((size_t)b * CHN + hh * 64) * T;
#pragma unroll
    for (int nt = 0; nt < 8; nt++) {
        int c0 = nt * 8 + 2 * q;
        ab[(size_t)c0 * T + t0 + rb + g]           = o[nt][0] * inv_a;
        ab[(size_t)(c0 + 1) * T + t0 + rb + g]     = o[nt][1] * inv_a;
        ab[(size_t)c0 * T + t0 + rb + g + 8]       = o[nt][2] * inv_b;
        ab[(size_t)(c0 + 1) * T + t0 + rb + g + 8] = o[nt][3] * inv_b;
    }
}

// ---------------------------------------------------------------------------
extern "C" void kernel_launch(void* const* d_in, const int* in_sizes, int n_in,
                              void* d_out, int out_size) {
    const float* x      = (const float*)d_in[0];
    const float* nw     = (const float*)d_in[1];
    const float* qkv_w  = (const float*)d_in[2];
    const float* qkv_b  = (const float*)d_in[3];
    const float* proj_w = (const float*)d_in[4];
    const float* proj_b = (const float*)d_in[5];
    float* out = (float*)d_out;

    const int QKV_SMEM  = 14336 * 4;  // 57344
    const int PROJ_SMEM = 9216 * 4;   // 36864
    const int ATT_SMEM  = 26368 * 4;  // 105472
    static bool init = false;
    if (!init) {
        cudaFuncSetAttribute(gemm_mma<true>,  cudaFuncAttributeMaxDynamicSharedMemorySize, QKV_SMEM);
        cudaFuncSetAttribute(gemm_mma<false>, cudaFuncAttributeMaxDynamicSharedMemorySize, PROJ_SMEM);
        cudaFuncSetAttribute(attn_mma,        cudaFuncAttributeMaxDynamicSharedMemorySize, ATT_SMEM);
        cudaFuncSetAttribute(gemm_mma<true>,  cudaFuncAttributePreferredSharedMemoryCarveout, 100);
        cudaFuncSetAttribute(gemm_mma<false>, cudaFuncAttributePreferredSharedMemoryCarveout, 100);
        cudaFuncSetAttribute(attn_mma,        cudaFuncAttributePreferredSharedMemoryCarveout, 100);
        init = true;
    }
    rms_kernel<<<256, 256>>>(x);
    gemm_mma<true><<<dim3(32, 12, 2), 256, QKV_SMEM>>>(qkv_w, x, nw, qkv_b, nullptr, nullptr);
    attn_mma<<<dim3(32, 16), 256, ATT_SMEM>>>();
    gemm_mma<false><<<dim3(32, 4, 2), 256, PROJ_SMEM>>>(proj_w, nullptr, nullptr, proj_b, x, out);
}